// round 5
// baseline (speedup 1.0000x reference)
#include <cuda_runtime.h>
#include <cuda_bf16.h>
#include <cstdint>

// ---------------------------------------------------------------------------
constexpr int BATCH = 4;
constexpr int SEQ   = 2048;
constexpr int HID   = 1024;
constexpr int NHEAD = 16;
constexpr int HDIM  = 64;
constexpr int MROWS = BATCH * SEQ;                       // 8192
constexpr long long OUT_ELEMS = (long long)MROWS * HID;  // 8,388,608

// GEMM tiles: 32-col chunks, rows padded to 40 bf16 (80 B) -> conflict-free ldsm
constexpr int LDT = 40;
constexpr int TILE_B = 128 * LDT * 2;     // 10240
constexpr int GBUF   = 4 * TILE_B;        // Ah,Al,Bh,Bl per chunk buffer
constexpr int SMEM_G = 2 * GBUF;          // 81920

// Attention tiles: 64-col rows padded to 72 bf16 (144 B)
constexpr int LDA_B  = 144;
constexpr int ATILE  = 128 * LDA_B;       // 18432
// smem offsets
constexpr int OQH = 0, OQL = ATILE;
constexpr int OKH0 = 2 * ATILE, OKL0 = 3 * ATILE, OKH1 = 4 * ATILE, OKL1 = 5 * ATILE;
constexpr int OVH0 = 6 * ATILE, OVL0 = 7 * ATILE, OVH1 = 8 * ATILE, OVL1 = 9 * ATILE;
constexpr int SMEM_ATTN = 10 * ATILE;     // 184320

// ---------------------------------------------------------------------------
// Prepped bf16 hi/lo operands (device globals; no runtime allocation)
// ---------------------------------------------------------------------------
__device__ __nv_bfloat16 g_xh[MROWS * HID], g_xl[MROWS * HID];
__device__ __nv_bfloat16 g_wh[4 * HID * HID], g_wl[4 * HID * HID];
__device__ __nv_bfloat16 g_qh[64 * SEQ * HDIM], g_ql[64 * SEQ * HDIM];
__device__ __nv_bfloat16 g_kh[64 * SEQ * HDIM], g_kl[64 * SEQ * HDIM];
__device__ __nv_bfloat16 g_vh[64 * SEQ * HDIM], g_vl[64 * SEQ * HDIM];
__device__ __nv_bfloat16 g_ch[MROWS * HID], g_cl[MROWS * HID];

// ---------------------------------------------------------------------------
__device__ __forceinline__ uint32_t smem_u32(const void* p) {
    uint32_t a;
    asm("{ .reg .u64 t; cvta.to.shared.u64 t, %1; cvt.u32.u64 %0, t; }"
        : "=r"(a) : "l"(p));
    return a;
}

__device__ __forceinline__ void ldsm4(uint32_t* r, uint32_t a) {
    asm volatile("ldmatrix.sync.aligned.m8n8.x4.shared.b16 {%0,%1,%2,%3}, [%4];"
                 : "=r"(r[0]), "=r"(r[1]), "=r"(r[2]), "=r"(r[3]) : "r"(a));
}
__device__ __forceinline__ void ldsm4t(uint32_t* r, uint32_t a) {
    asm volatile("ldmatrix.sync.aligned.m8n8.x4.trans.shared.b16 {%0,%1,%2,%3}, [%4];"
                 : "=r"(r[0]), "=r"(r[1]), "=r"(r[2]), "=r"(r[3]) : "r"(a));
}

#define MMA_BF16(d, a, b0, b1)                                              \
    asm volatile(                                                           \
        "mma.sync.aligned.m16n8k16.row.col.f32.bf16.bf16.f32 "              \
        "{%0,%1,%2,%3}, {%4,%5,%6,%7}, {%8,%9}, {%0,%1,%2,%3};"             \
        : "+f"((d)[0]), "+f"((d)[1]), "+f"((d)[2]), "+f"((d)[3])            \
        : "r"((a)[0]), "r"((a)[1]), "r"((a)[2]), "r"((a)[3]),               \
          "r"(b0), "r"(b1))

__device__ __forceinline__ void cp16(uint32_t dst, const void* src) {
    asm volatile("cp.async.cg.shared.global [%0], [%1], 16;" :: "r"(dst), "l"(src));
}
#define CP_COMMIT asm volatile("cp.async.commit_group;" ::: "memory")
#define CP_WAIT1  asm volatile("cp.async.wait_group 1;" ::: "memory")
#define CP_WAIT0  asm volatile("cp.async.wait_group 0;" ::: "memory")

__device__ __forceinline__ void pack_hl(float x, float y, uint32_t& h, uint32_t& l) {
    __nv_bfloat16 hx = __float2bfloat16(x);
    __nv_bfloat16 hy = __float2bfloat16(y);
    __nv_bfloat16 lx = __float2bfloat16(x - __bfloat162float(hx));
    __nv_bfloat16 ly = __float2bfloat16(y - __bfloat162float(hy));
    h = ((uint32_t)__bfloat16_as_ushort(hy) << 16) | __bfloat16_as_ushort(hx);
    l = ((uint32_t)__bfloat16_as_ushort(ly) << 16) | __bfloat16_as_ushort(lx);
}

// ---------------------------------------------------------------------------
// prep: split X and the 4 weight matrices into bf16 hi/lo once.
// ---------------------------------------------------------------------------
__global__ void __launch_bounds__(256) prep(
    const float* __restrict__ X,  const float* __restrict__ Wq,
    const float* __restrict__ Wk, const float* __restrict__ Wv,
    const float* __restrict__ Wo)
{
    const long long NX = (long long)MROWS * HID;
    long long i = (long long)blockIdx.x * 256 + threadIdx.x;
    float v; __nv_bfloat16 *dh, *dl; long long o;
    if (i < NX) {
        v = X[i]; dh = g_xh; dl = g_xl; o = i;
    } else {
        long long j = i - NX;
        int w = (int)(j >> 20);
        long long r = j & 1048575;
        if (w == 0) v = Wq[r]; else if (w == 1) v = Wk[r];
        else if (w == 2) v = Wv[r]; else v = Wo[r];
        dh = g_wh; dl = g_wl; o = j;
    }
    __nv_bfloat16 hb = __float2bfloat16(v);
    dh[o] = hb;
    dl[o] = __float2bfloat16(v - __bfloat162float(hb));
}

// ---------------------------------------------------------------------------
// Split-bf16 warp MMA over one 32-wide K chunk (GEMM kernels, LDT=40).
// ---------------------------------------------------------------------------
template <int MF, int NF>
__device__ __forceinline__ void mma_chunk(float (&acc)[MF][NF][4],
                                          uint32_t aHi, uint32_t aLo,
                                          uint32_t bHi, uint32_t bLo,
                                          int mbase, int nbase, int lane)
{
    const int r16 = lane & 15;
    const int koL = (lane >> 4) * 16;
#pragma unroll
    for (int ks = 0; ks < 2; ks++) {
        const int kb = ks * 32 + koL;
        uint32_t FA[4 * MF], FB[2 * NF], FC[2 * NF];
#pragma unroll
        for (int mf = 0; mf < MF; mf++)
            ldsm4(&FA[4 * mf], aHi + (mbase + mf * 16 + r16) * (LDT * 2) + kb);
#pragma unroll
        for (int nb = 0; nb < NF / 2; nb++)
            ldsm4(&FB[4 * nb], bHi + (nbase + nb * 16 + r16) * (LDT * 2) + kb);
#pragma unroll
        for (int mf = 0; mf < MF; mf++)
#pragma unroll
            for (int nf = 0; nf < NF; nf++)
                MMA_BF16(acc[mf][nf], &FA[4 * mf],
                         FB[4 * (nf >> 1) + (nf & 1)], FB[4 * (nf >> 1) + 2 + (nf & 1)]);
#pragma unroll
        for (int nb = 0; nb < NF / 2; nb++)
            ldsm4(&FC[4 * nb], bLo + (nbase + nb * 16 + r16) * (LDT * 2) + kb);
#pragma unroll
        for (int mf = 0; mf < MF; mf++)
#pragma unroll
            for (int nf = 0; nf < NF; nf++)
                MMA_BF16(acc[mf][nf], &FA[4 * mf],
                         FC[4 * (nf >> 1) + (nf & 1)], FC[4 * (nf >> 1) + 2 + (nf & 1)]);
#pragma unroll
        for (int mf = 0; mf < MF; mf++)
            ldsm4(&FA[4 * mf], aLo + (mbase + mf * 16 + r16) * (LDT * 2) + kb);
#pragma unroll
        for (int mf = 0; mf < MF; mf++)
#pragma unroll
            for (int nf = 0; nf < NF; nf++)
                MMA_BF16(acc[mf][nf], &FA[4 * mf],
                         FB[4 * (nf >> 1) + (nf & 1)], FB[4 * (nf >> 1) + 2 + (nf & 1)]);
    }
}

// cp.async a 128x32 bf16 tile (ld = HID) into LDT=40 smem
__device__ __forceinline__ void cp_tile32(const __nv_bfloat16* __restrict__ src,
                                          uint32_t dst, int tid) {
#pragma unroll
    for (int i = 0; i < 2; i++) {
        int id = tid + i * 256;
        int r = id >> 2, c = id & 3;
        cp16(dst + r * (LDT * 2) + c * 16, src + (long long)r * HID + c * 8);
    }
}

// ---------------------------------------------------------------------------
// QKV projection from prepped bf16: C = X W^T + b -> q/k/v hi/lo [bh][s][d]
// grid(8, 64, 3), 256 thr
// ---------------------------------------------------------------------------
__global__ void __launch_bounds__(256, 2) mm_qkv(
    const float* __restrict__ bq, const float* __restrict__ bk,
    const float* __restrict__ bv)
{
    extern __shared__ char sm[];
    const int z = blockIdx.z;
    const float* bias = (z == 0) ? bq : (z == 1) ? bk : bv;
    __nv_bfloat16* dsth = (z == 0) ? g_qh : (z == 1) ? g_kh : g_vh;
    __nv_bfloat16* dstl = (z == 0) ? g_ql : (z == 1) ? g_kl : g_vl;

    const int tid = threadIdx.x, lane = tid & 31, wid = tid >> 5;
    const int mw = wid >> 2, nw = wid & 3;
    const int m0 = blockIdx.y * 128, n0 = blockIdx.x * 128;
    const __nv_bfloat16* Ah = g_xh + (long long)m0 * HID;
    const __nv_bfloat16* Al = g_xl + (long long)m0 * HID;
    const __nv_bfloat16* Bh = g_wh + (long long)z * HID * HID + (long long)n0 * HID;
    const __nv_bfloat16* Bl = g_wl + (long long)z * HID * HID + (long long)n0 * HID;
    const uint32_t s0 = smem_u32(sm);

    float acc[4][4][4];
#pragma unroll
    for (int i = 0; i < 4; i++)
#pragma unroll
        for (int j = 0; j < 4; j++)
#pragma unroll
            for (int q = 0; q < 4; q++) acc[i][j][q] = 0.f;

    cp_tile32(Ah, s0 + 0 * TILE_B, tid);
    cp_tile32(Al, s0 + 1 * TILE_B, tid);
    cp_tile32(Bh, s0 + 2 * TILE_B, tid);
    cp_tile32(Bl, s0 + 3 * TILE_B, tid);
    CP_COMMIT;

    for (int c = 0; c < 32; c++) {
        if (c + 1 < 32) {
            uint32_t nb = s0 + ((c + 1) & 1) * GBUF;
            cp_tile32(Ah + (c + 1) * 32, nb + 0 * TILE_B, tid);
            cp_tile32(Al + (c + 1) * 32, nb + 1 * TILE_B, tid);
            cp_tile32(Bh + (c + 1) * 32, nb + 2 * TILE_B, tid);
            cp_tile32(Bl + (c + 1) * 32, nb + 3 * TILE_B, tid);
            CP_COMMIT;
            CP_WAIT1;
        } else {
            CP_WAIT0;
        }
        __syncthreads();
        uint32_t buf = s0 + (c & 1) * GBUF;
        mma_chunk<4, 4>(acc, buf, buf + TILE_B, buf + 2 * TILE_B, buf + 3 * TILE_B,
                        mw * 64, nw * 32, lane);
        __syncthreads();
    }

    const int g = lane >> 2, tig = lane & 3;
#pragma unroll
    for (int mf = 0; mf < 4; mf++) {
#pragma unroll
        for (int half = 0; half < 2; half++) {
            const int m = m0 + mw * 64 + mf * 16 + g + half * 8;
            const int b = m >> 11, s = m & 2047;
#pragma unroll
            for (int nf = 0; nf < 4; nf++) {
                const int n = n0 + nw * 32 + nf * 8 + tig * 2;
                const int h = n >> 6, d = n & 63;
                float vx = acc[mf][nf][half * 2 + 0] + bias[n + 0];
                float vy = acc[mf][nf][half * 2 + 1] + bias[n + 1];
                uint32_t hw, lw;
                pack_hl(vx, vy, hw, lw);
                long long idx = ((long long)(b * NHEAD + h) * SEQ + s) * HDIM + d;
                *(uint32_t*)(dsth + idx) = hw;
                *(uint32_t*)(dstl + idx) = lw;
            }
        }
    }
}

// ---------------------------------------------------------------------------
// Fused two-pass attention: S = Q K^T, P = softmax(S) (written once),
// ctx = P V (bf16 hi/lo out).  grid(16, 64), 256 thr, 8 warps x 16 rows.
// ---------------------------------------------------------------------------
__device__ __forceinline__ void cp_tile64(const __nv_bfloat16* __restrict__ src,
                                          uint32_t dst, int tid) {
#pragma unroll
    for (int i = 0; i < 4; i++) {
        int id = tid + i * 256;
        int r = id >> 3, c = id & 7;
        cp16(dst + r * LDA_B + c * 16, src + (long long)r * HDIM + c * 8);
    }
}

// split S for one 16-col block (nfp): acc[0..3] cols +0..7, acc[4..7] cols +8..15
__device__ __forceinline__ void s_tile_nfp(float* acc,
                                           const uint32_t* FQh, const uint32_t* FQl,
                                           uint32_t kh, uint32_t kl, int nfp, int lane)
{
    const int r16 = lane & 15;
    const int koL = (lane >> 4) * 16;
    const uint32_t rowoff = (uint32_t)(nfp * 16 + r16) * LDA_B;
#pragma unroll
    for (int ks = 0; ks < 4; ks++) {
        uint32_t FBh[4], FBl[4];
        ldsm4(FBh, kh + rowoff + ks * 32 + koL);
        ldsm4(FBl, kl + rowoff + ks * 32 + koL);
        MMA_BF16(acc,     &FQh[4 * ks], FBh[0], FBh[2]);
        MMA_BF16(acc + 4, &FQh[4 * ks], FBh[1], FBh[3]);
        MMA_BF16(acc,     &FQh[4 * ks], FBl[0], FBl[2]);
        MMA_BF16(acc + 4, &FQh[4 * ks], FBl[1], FBl[3]);
        MMA_BF16(acc,     &FQl[4 * ks], FBh[0], FBh[2]);
        MMA_BF16(acc + 4, &FQl[4 * ks], FBh[1], FBh[3]);
    }
}

__global__ void __launch_bounds__(256, 1) attn(float* __restrict__ probs)
{
    extern __shared__ char sm[];
    const int tid = threadIdx.x, lane = tid & 31, w = tid >> 5;
    const int g = lane >> 2, tig = lane & 3;
    const int bh = blockIdx.y;
    const int m0 = blockIdx.x * 128;
    const uint32_t s0 = smem_u32(sm);

    const __nv_bfloat16* Qh = g_qh + ((long long)bh * SEQ + m0) * HDIM;
    const __nv_bfloat16* Ql = g_ql + ((long long)bh * SEQ + m0) * HDIM;
    const __nv_bfloat16* Kh = g_kh + (long long)bh * SEQ * HDIM;
    const __nv_bfloat16* Kl = g_kl + (long long)bh * SEQ * HDIM;
    const __nv_bfloat16* Vh = g_vh + (long long)bh * SEQ * HDIM;
    const __nv_bfloat16* Vl = g_vl + (long long)bh * SEQ * HDIM;
    float* C = probs + (long long)bh * SEQ * SEQ;

    // Q tile + first K tile
    cp_tile64(Qh, s0 + OQH, tid);
    cp_tile64(Ql, s0 + OQL, tid);
    cp_tile64(Kh, s0 + OKH0, tid);
    cp_tile64(Kl, s0 + OKL0, tid);
    CP_COMMIT;
    CP_WAIT0;
    __syncthreads();

    // Q fragments (constant for whole kernel)
    uint32_t FQh[16], FQl[16];
    {
        const uint32_t arow = (uint32_t)(w * 16 + (lane & 15)) * LDA_B;
        const uint32_t koL = (lane >> 4) * 16;
#pragma unroll
        for (int ks = 0; ks < 4; ks++) {
            ldsm4(&FQh[4 * ks], s0 + OQH + arow + ks * 32 + koL);
            ldsm4(&FQl[4 * ks], s0 + OQL + arow + ks * 32 + koL);
        }
    }

    // ---------------- pass A: row sums of exp(S) ----------------
    float sum0 = 0.f, sum1 = 0.f;
    for (int j = 0; j < 16; j++) {
        if (j + 1 < 16) {
            uint32_t kb = s0 + (((j + 1) & 1) ? OKH1 : OKH0);
            cp_tile64(Kh + (long long)(j + 1) * 128 * HDIM, kb, tid);
            cp_tile64(Kl + (long long)(j + 1) * 128 * HDIM, kb + ATILE, tid);
            CP_COMMIT;
            CP_WAIT1;
        } else {
            CP_WAIT0;
        }
        __syncthreads();
        const uint32_t kh = s0 + ((j & 1) ? OKH1 : OKH0);
        const uint32_t kl = kh + ATILE;
#pragma unroll
        for (int nfp = 0; nfp < 8; nfp++) {
            float acc[8] = {0.f, 0.f, 0.f, 0.f, 0.f, 0.f, 0.f, 0.f};
            s_tile_nfp(acc, FQh, FQl, kh, kl, nfp, lane);
            sum0 += __expf(acc[0]) + __expf(acc[1]) + __expf(acc[4]) + __expf(acc[5]);
            sum1 += __expf(acc[2]) + __expf(acc[3]) + __expf(acc[6]) + __expf(acc[7]);
        }
        __syncthreads();
    }
#pragma unroll
    for (int o = 1; o <= 2; o <<= 1) {
        sum0 += __shfl_xor_sync(0xffffffffu, sum0, o);
        sum1 += __shfl_xor_sync(0xffffffffu, sum1, o);
    }
    const float ri0 = 1.0f / sum0;
    const float ri1 = 1.0f / sum1;

    // ---------------- pass B: write P, accumulate ctx = P V ----------------
    float ctx[8][4];
#pragma unroll
    for (int i = 0; i < 8; i++)
#pragma unroll
        for (int q = 0; q < 4; q++) ctx[i][q] = 0.f;

    cp_tile64(Kh, s0 + OKH0, tid);
    cp_tile64(Kl, s0 + OKL0, tid);
    cp_tile64(Vh, s0 + OVH0, tid);
    cp_tile64(Vl, s0 + OVL0, tid);
    CP_COMMIT;

    const long long rowg = m0 + w * 16 + g;

    for (int j = 0; j < 16; j++) {
        if (j + 1 < 16) {
            uint32_t kb = s0 + (((j + 1) & 1) ? OKH1 : OKH0);
            uint32_t vb = s0 + (((j + 1) & 1) ? OVH1 : OVH0);
            cp_tile64(Kh + (long long)(j + 1) * 128 * HDIM, kb, tid);
            cp_tile64(Kl + (long long)(j + 1) * 128 * HDIM, kb + ATILE, tid);
            cp_tile64(Vh + (long long)(j + 1) * 128 * HDIM, vb, tid);
            cp_tile64(Vl + (long long)(j + 1) * 128 * HDIM, vb + ATILE, tid);
            CP_COMMIT;
            CP_WAIT1;
        } else {
            CP_WAIT0;
        }
        __syncthreads();
        const uint32_t kh = s0 + ((j & 1) ? OKH1 : OKH0);
        const uint32_t kl = kh + ATILE;
        const uint32_t vh = s0 + ((j & 1) ? OVH1 : OVH0);
        const uint32_t vl = vh + ATILE;
        // V ldsm.trans base address for this thread
        const uint32_t vlanerow = (uint32_t)((lane & 7) + ((lane >> 4) & 1) * 8) * LDA_B
                                  + ((lane >> 3) & 1) * 16;

#pragma unroll
        for (int nfp = 0; nfp < 8; nfp++) {
            float acc[8] = {0.f, 0.f, 0.f, 0.f, 0.f, 0.f, 0.f, 0.f};
            s_tile_nfp(acc, FQh, FQl, kh, kl, nfp, lane);
            // normalized probs
            float pE0 = __expf(acc[0]) * ri0, pE1 = __expf(acc[1]) * ri0;
            float pE2 = __expf(acc[2]) * ri1, pE3 = __expf(acc[3]) * ri1;
            float pO0 = __expf(acc[4]) * ri0, pO1 = __expf(acc[5]) * ri0;
            float pO2 = __expf(acc[6]) * ri1, pO3 = __expf(acc[7]) * ri1;
            // write P (streaming)
            float* Cr = C + rowg * SEQ + j * 128 + nfp * 16 + tig * 2;
            __stcs((float2*)Cr,                 make_float2(pE0, pE1));
            __stcs((float2*)(Cr + 8),           make_float2(pO0, pO1));
            __stcs((float2*)(Cr + 8 * SEQ),     make_float2(pE2, pE3));
            __stcs((float2*)(Cr + 8 * SEQ + 8), make_float2(pO2, pO3));
            // convert to A-fragments (k16 slice = this 16-col block)
            uint32_t PAh[4], PAl[4];
            pack_hl(pE0, pE1, PAh[0], PAl[0]);
            pack_hl(pE2, pE3, PAh[1], PAl[1]);
            pack_hl(pO0, pO1, PAh[2], PAl[2]);
            pack_hl(pO2, pO3, PAh[3], PAl[3]);
            // V fragments for this k-slice (s rows nfp*16..+15), d = 0..63
            uint32_t FVh[16], FVl[16];
            const uint32_t vbase = (uint32_t)(nfp * 16) * LDA_B + vlanerow;
#pragma unroll
            for (int gd = 0; gd < 4; gd++) {
                ldsm4t(&FVh[4 * gd], vh + vbase + gd * 32);
                ldsm4t(&FVl[4 * gd], vl + vbase + gd * 32);
            }
#pragma unroll
            for (int dnf = 0; dnf < 8; dnf++) {
                const int j0 = 4 * (dnf >> 1) + (dnf & 1);
                MMA_BF16(ctx[dnf], PAh, FVh[j0], FVh[j0 + 2]);
                MMA_BF16(ctx[dnf], PAh, FVl[j0], FVl[j0 + 2]);
                MMA_BF16(ctx[dnf], PAl, FVh[j0], FVh[j0 + 2]);
            }
        }
        __syncthreads();
    }

    // ctx epilogue -> bf16 hi/lo [b][s][h*64+d]
    const int b = bh >> 4, h = bh & 15;
    const int s = m0 + w * 16 + g;
    const long long base = ((long long)(b * SEQ + s)) * HID + h * HDIM;
#pragma unroll
    for (int dnf = 0; dnf < 8; dnf++) {
        const int d = dnf * 8 + tig * 2;
        uint32_t hw, lw;
        pack_hl(ctx[dnf][0], ctx[dnf][1], hw, lw);
        *(uint32_t*)(g_ch + base + d) = hw;
        *(uint32_t*)(g_cl + base + d) = lw;
        pack_hl(ctx[dnf][2], ctx[dnf][3], hw, lw);
        *(uint32_t*)(g_ch + base + 8LL * HID + d) = hw;
        *(uint32_t*)(g_cl + base + 8LL * HID + d) = lw;
    }
}

// ---------------------------------------------------------------------------
// Output projection + residual: out = ctx Wo^T + bo + hidden.  grid(8, 64).
// ---------------------------------------------------------------------------
__global__ void __launch_bounds__(256, 2) mm_out(
    const float* __restrict__ bo, const float* __restrict__ hidden,
    float* __restrict__ out)
{
    extern __shared__ char sm[];
    const int tid = threadIdx.x, lane = tid & 31, wid = tid >> 5;
    const int mw = wid >> 2, nw = wid & 3;
    const int m0 = blockIdx.y * 128, n0 = blockIdx.x * 128;
    const __nv_bfloat16* Ah = g_ch + (long long)m0 * HID;
    const __nv_bfloat16* Al = g_cl + (long long)m0 * HID;
    const __nv_bfloat16* Bh = g_wh + 3LL * HID * HID + (long long)n0 * HID;
    const __nv_bfloat16* Bl = g_wl + 3LL * HID * HID + (long long)n0 * HID;
    const uint32_t s0 = smem_u32(sm);

    float acc[4][4][4];
#pragma unroll
    for (int i = 0; i < 4; i++)
#pragma unroll
        for (int j = 0; j < 4; j++)
#pragma unroll
            for (int q = 0; q < 4; q++) acc[i][j][q] = 0.f;

    cp_tile32(Ah, s0 + 0 * TILE_B, tid);
    cp_tile32(Al, s0 + 1 * TILE_B, tid);
    cp_tile32(Bh, s0 + 2 * TILE_B, tid);
    cp_tile32(Bl, s0 + 3 * TILE_B, tid);
    CP_COMMIT;

    for (int c = 0; c < 32; c++) {
        if (c + 1 < 32) {
            uint32_t nb = s0 + ((c + 1) & 1) * GBUF;
            cp_tile32(Ah + (c + 1) * 32, nb + 0 * TILE_B, tid);
            cp_tile32(Al + (c + 1) * 32, nb + 1 * TILE_B, tid);
            cp_tile32(Bh + (c + 1) * 32, nb + 2 * TILE_B, tid);
            cp_tile32(Bl + (c + 1) * 32, nb + 3 * TILE_B, tid);
            CP_COMMIT;
            CP_WAIT1;
        } else {
            CP_WAIT0;
        }
        __syncthreads();
        uint32_t buf = s0 + (c & 1) * GBUF;
        mma_chunk<4, 4>(acc, buf, buf + TILE_B, buf + 2 * TILE_B, buf + 3 * TILE_B,
                        mw * 64, nw * 32, lane);
        __syncthreads();
    }

    const int g = lane >> 2, tig = lane & 3;
#pragma unroll
    for (int mf = 0; mf < 4; mf++) {
#pragma unroll
        for (int half = 0; half < 2; half++) {
            const long long m = m0 + mw * 64 + mf * 16 + g + half * 8;
#pragma unroll
            for (int nf = 0; nf < 4; nf++) {
                const int n = n0 + nw * 32 + nf * 8 + tig * 2;
                float2 hd = *(const float2*)(hidden + m * HID + n);
                float2 st;
                st.x = acc[mf][nf][half * 2 + 0] + bo[n + 0] + hd.x;
                st.y = acc[mf][nf][half * 2 + 1] + bo[n + 1] + hd.y;
                *(float2*)(out + m * HID + n) = st;
            }
        }
    }
}

// ---------------------------------------------------------------------------
extern "C" void kernel_launch(void* const* d_in, const int* in_sizes, int n_in,
                              void* d_out, int out_size)
{
    const float* X  = (const float*)d_in[0];
    const float* Wq = (const float*)d_in[1];
    const float* bq = (const float*)d_in[2];
    const float* Wk = (const float*)d_in[3];
    const float* bk = (const float*)d_in[4];
    const float* Wv = (const float*)d_in[5];
    const float* bv = (const float*)d_in[6];
    const float* Wo = (const float*)d_in[7];
    const float* bo = (const float*)d_in[8];

    float* out   = (float*)d_out;
    float* probs = out + OUT_ELEMS;

    cudaFuncSetAttribute(mm_qkv, cudaFuncAttributeMaxDynamicSharedMemorySize, SMEM_G);
    cudaFuncSetAttribute(mm_out, cudaFuncAttributeMaxDynamicSharedMemorySize, SMEM_G);
    cudaFuncSetAttribute(attn,   cudaFuncAttributeMaxDynamicSharedMemorySize, SMEM_ATTN);

    const long long NPREP = (long long)MROWS * HID + 4LL * HID * HID;
    prep<<<(unsigned)((NPREP + 255) / 256), 256>>>(X, Wq, Wk, Wv, Wo);
    mm_qkv<<<dim3(HID / 128, MROWS / 128, 3), 256, SMEM_G>>>(bq, bk, bv);
    attn<<<dim3(SEQ / 128, BATCH * NHEAD), 256, SMEM_ATTN>>>(probs);
    mm_out<<<dim3(HID / 128, MROWS / 128), 256, SMEM_G>>>(bo, X, out);
}

// round 7
// speedup vs baseline: 1.0117x; 1.0117x over previous
#include <cuda_runtime.h>
#include <cuda_bf16.h>
#include <cstdint>

// ---------------------------------------------------------------------------
constexpr int BATCH = 4;
constexpr int SEQ   = 2048;
constexpr int HID   = 1024;
constexpr int NHEAD = 16;
constexpr int HDIM  = 64;
constexpr int MROWS = BATCH * SEQ;                       // 8192
constexpr long long OUT_ELEMS = (long long)MROWS * HID;  // 8,388,608

// GEMM tiles: 32-col chunks, rows padded to 40 bf16 (80 B)
constexpr int LDT = 40;
constexpr int TILE_B = 128 * LDT * 2;     // 10240
constexpr int GBUF   = 4 * TILE_B;        // Ah,Al,Bh,Bl
constexpr int SMEM_G = 2 * GBUF;          // 81920

// Attention tiles: 64-col rows padded to 72 bf16 (144 B)
constexpr int LDA_B  = 144;
constexpr int KTILE  = 128 * LDA_B;       // 18432 (one 128x64 bf16 tile)
constexpr int OQH = 0;                    // Q hi: 256 rows
constexpr int OQL = 256 * LDA_B;          // 36864
constexpr int OSLOT = 2 * 256 * LDA_B;    // 73728: 4 slots x 36864 (hi, lo)
constexpr int SLOT_SZ = 2 * KTILE;        // 36864
constexpr int SMEM_ATTN = OSLOT + 4 * SLOT_SZ;  // 221184

// ---------------------------------------------------------------------------
// Prepped bf16 hi/lo operands
// ---------------------------------------------------------------------------
__device__ __nv_bfloat16 g_xh[MROWS * HID], g_xl[MROWS * HID];
__device__ __nv_bfloat16 g_wh[4 * HID * HID], g_wl[4 * HID * HID];
__device__ __nv_bfloat16 g_qh[64 * SEQ * HDIM], g_ql[64 * SEQ * HDIM];
__device__ __nv_bfloat16 g_kh[64 * SEQ * HDIM], g_kl[64 * SEQ * HDIM];
__device__ __nv_bfloat16 g_vh[64 * SEQ * HDIM], g_vl[64 * SEQ * HDIM];
__device__ __nv_bfloat16 g_ch[MROWS * HID], g_cl[MROWS * HID];

// ---------------------------------------------------------------------------
__device__ __forceinline__ uint32_t smem_u32(const void* p) {
    uint32_t a;
    asm("{ .reg .u64 t; cvta.to.shared.u64 t, %1; cvt.u32.u64 %0, t; }"
        : "=r"(a) : "l"(p));
    return a;
}

__device__ __forceinline__ void ldsm4(uint32_t* r, uint32_t a) {
    asm volatile("ldmatrix.sync.aligned.m8n8.x4.shared.b16 {%0,%1,%2,%3}, [%4];"
                 : "=r"(r[0]), "=r"(r[1]), "=r"(r[2]), "=r"(r[3]) : "r"(a));
}
__device__ __forceinline__ void ldsm4t(uint32_t* r, uint32_t a) {
    asm volatile("ldmatrix.sync.aligned.m8n8.x4.trans.shared.b16 {%0,%1,%2,%3}, [%4];"
                 : "=r"(r[0]), "=r"(r[1]), "=r"(r[2]), "=r"(r[3]) : "r"(a));
}

#define MMA_BF16(d, a, b0, b1)                                              \
    asm volatile(                                                           \
        "mma.sync.aligned.m16n8k16.row.col.f32.bf16.bf16.f32 "              \
        "{%0,%1,%2,%3}, {%4,%5,%6,%7}, {%8,%9}, {%0,%1,%2,%3};"             \
        : "+f"((d)[0]), "+f"((d)[1]), "+f"((d)[2]), "+f"((d)[3])            \
        : "r"((a)[0]), "r"((a)[1]), "r"((a)[2]), "r"((a)[3]),               \
          "r"(b0), "r"(b1))

__device__ __forceinline__ void cp16(uint32_t dst, const void* src) {
    asm volatile("cp.async.cg.shared.global [%0], [%1], 16;" :: "r"(dst), "l"(src));
}
#define CP_COMMIT asm volatile("cp.async.commit_group;" ::: "memory")
#define CP_WAIT3  asm volatile("cp.async.wait_group 3;" ::: "memory")
#define CP_WAIT1  asm volatile("cp.async.wait_group 1;" ::: "memory")
#define CP_WAIT0  asm volatile("cp.async.wait_group 0;" ::: "memory")

__device__ __forceinline__ void pack_hl(float x, float y, uint32_t& h, uint32_t& l) {
    __nv_bfloat16 hx = __float2bfloat16(x);
    __nv_bfloat16 hy = __float2bfloat16(y);
    __nv_bfloat16 lx = __float2bfloat16(x - __bfloat162float(hx));
    __nv_bfloat16 ly = __float2bfloat16(y - __bfloat162float(hy));
    h = ((uint32_t)__bfloat16_as_ushort(hy) << 16) | __bfloat16_as_ushort(hx);
    l = ((uint32_t)__bfloat16_as_ushort(ly) << 16) | __bfloat16_as_ushort(lx);
}

// ---------------------------------------------------------------------------
// prep: split X and the 4 weight matrices into bf16 hi/lo once.
// ---------------------------------------------------------------------------
__global__ void __launch_bounds__(256) prep(
    const float* __restrict__ X,  const float* __restrict__ Wq,
    const float* __restrict__ Wk, const float* __restrict__ Wv,
    const float* __restrict__ Wo)
{
    const long long NX = (long long)MROWS * HID;
    long long i = (long long)blockIdx.x * 256 + threadIdx.x;
    float v; __nv_bfloat16 *dh, *dl; long long o;
    if (i < NX) {
        v = X[i]; dh = g_xh; dl = g_xl; o = i;
    } else {
        long long j = i - NX;
        int w = (int)(j >> 20);
        long long r = j & 1048575;
        if (w == 0) v = Wq[r]; else if (w == 1) v = Wk[r];
        else if (w == 2) v = Wv[r]; else v = Wo[r];
        dh = g_wh; dl = g_wl; o = j;
    }
    __nv_bfloat16 hb = __float2bfloat16(v);
    dh[o] = hb;
    dl[o] = __float2bfloat16(v - __bfloat162float(hb));
}

// ---------------------------------------------------------------------------
// Split-bf16 warp MMA over one 32-wide K chunk (GEMM kernels).
// ---------------------------------------------------------------------------
template <int MF, int NF>
__device__ __forceinline__ void mma_chunk(float (&acc)[MF][NF][4],
                                          uint32_t aHi, uint32_t aLo,
                                          uint32_t bHi, uint32_t bLo,
                                          int mbase, int nbase, int lane)
{
    const int r16 = lane & 15;
    const int koL = (lane >> 4) * 16;
#pragma unroll
    for (int ks = 0; ks < 2; ks++) {
        const int kb = ks * 32 + koL;
        uint32_t FA[4 * MF], FB[2 * NF], FC[2 * NF];
#pragma unroll
        for (int mf = 0; mf < MF; mf++)
            ldsm4(&FA[4 * mf], aHi + (mbase + mf * 16 + r16) * (LDT * 2) + kb);
#pragma unroll
        for (int nb = 0; nb < NF / 2; nb++)
            ldsm4(&FB[4 * nb], bHi + (nbase + nb * 16 + r16) * (LDT * 2) + kb);
#pragma unroll
        for (int mf = 0; mf < MF; mf++)
#pragma unroll
            for (int nf = 0; nf < NF; nf++)
                MMA_BF16(acc[mf][nf], &FA[4 * mf],
                         FB[4 * (nf >> 1) + (nf & 1)], FB[4 * (nf >> 1) + 2 + (nf & 1)]);
#pragma unroll
        for (int nb = 0; nb < NF / 2; nb++)
            ldsm4(&FC[4 * nb], bLo + (nbase + nb * 16 + r16) * (LDT * 2) + kb);
#pragma unroll
        for (int mf = 0; mf < MF; mf++)
#pragma unroll
            for (int nf = 0; nf < NF; nf++)
                MMA_BF16(acc[mf][nf], &FA[4 * mf],
                         FC[4 * (nf >> 1) + (nf & 1)], FC[4 * (nf >> 1) + 2 + (nf & 1)]);
#pragma unroll
        for (int mf = 0; mf < MF; mf++)
            ldsm4(&FA[4 * mf], aLo + (mbase + mf * 16 + r16) * (LDT * 2) + kb);
#pragma unroll
        for (int mf = 0; mf < MF; mf++)
#pragma unroll
            for (int nf = 0; nf < NF; nf++)
                MMA_BF16(acc[mf][nf], &FA[4 * mf],
                         FB[4 * (nf >> 1) + (nf & 1)], FB[4 * (nf >> 1) + 2 + (nf & 1)]);
    }
}

// cp.async a 128x32 bf16 tile (ld = HID) into LDT=40 smem (256 thr)
__device__ __forceinline__ void cp_tile32(const __nv_bfloat16* __restrict__ src,
                                          uint32_t dst, int tid) {
#pragma unroll
    for (int i = 0; i < 2; i++) {
        int id = tid + i * 256;
        int r = id >> 2, c = id & 3;
        cp16(dst + r * (LDT * 2) + c * 16, src + (long long)r * HID + c * 8);
    }
}

// ---------------------------------------------------------------------------
// QKV projection.  grid(8, 64, 3), 256 thr.
// ---------------------------------------------------------------------------
__global__ void __launch_bounds__(256, 2) mm_qkv(
    const float* __restrict__ bq, const float* __restrict__ bk,
    const float* __restrict__ bv)
{
    extern __shared__ char sm[];
    const int z = blockIdx.z;
    const float* bias = (z == 0) ? bq : (z == 1) ? bk : bv;
    __nv_bfloat16* dsth = (z == 0) ? g_qh : (z == 1) ? g_kh : g_vh;
    __nv_bfloat16* dstl = (z == 0) ? g_ql : (z == 1) ? g_kl : g_vl;

    const int tid = threadIdx.x, lane = tid & 31, wid = tid >> 5;
    const int mw = wid >> 2, nw = wid & 3;
    const int m0 = blockIdx.y * 128, n0 = blockIdx.x * 128;
    const __nv_bfloat16* Ah = g_xh + (long long)m0 * HID;
    const __nv_bfloat16* Al = g_xl + (long long)m0 * HID;
    const __nv_bfloat16* Bh = g_wh + (long long)z * HID * HID + (long long)n0 * HID;
    const __nv_bfloat16* Bl = g_wl + (long long)z * HID * HID + (long long)n0 * HID;
    const uint32_t s0 = smem_u32(sm);

    float acc[4][4][4];
#pragma unroll
    for (int i = 0; i < 4; i++)
#pragma unroll
        for (int j = 0; j < 4; j++)
#pragma unroll
            for (int q = 0; q < 4; q++) acc[i][j][q] = 0.f;

    cp_tile32(Ah, s0 + 0 * TILE_B, tid);
    cp_tile32(Al, s0 + 1 * TILE_B, tid);
    cp_tile32(Bh, s0 + 2 * TILE_B, tid);
    cp_tile32(Bl, s0 + 3 * TILE_B, tid);
    CP_COMMIT;

    for (int c = 0; c < 32; c++) {
        if (c + 1 < 32) {
            uint32_t nb = s0 + ((c + 1) & 1) * GBUF;
            cp_tile32(Ah + (c + 1) * 32, nb + 0 * TILE_B, tid);
            cp_tile32(Al + (c + 1) * 32, nb + 1 * TILE_B, tid);
            cp_tile32(Bh + (c + 1) * 32, nb + 2 * TILE_B, tid);
            cp_tile32(Bl + (c + 1) * 32, nb + 3 * TILE_B, tid);
            CP_COMMIT;
            CP_WAIT1;
        } else {
            CP_WAIT0;
        }
        __syncthreads();
        uint32_t buf = s0 + (c & 1) * GBUF;
        mma_chunk<4, 4>(acc, buf, buf + TILE_B, buf + 2 * TILE_B, buf + 3 * TILE_B,
                        mw * 64, nw * 32, lane);
        __syncthreads();
    }

    const int g = lane >> 2, tig = lane & 3;
#pragma unroll
    for (int mf = 0; mf < 4; mf++) {
#pragma unroll
        for (int half = 0; half < 2; half++) {
            const int m = m0 + mw * 64 + mf * 16 + g + half * 8;
            const int b = m >> 11, s = m & 2047;
#pragma unroll
            for (int nf = 0; nf < 4; nf++) {
                const int n = n0 + nw * 32 + nf * 8 + tig * 2;
                const int h = n >> 6, d = n & 63;
                float vx = acc[mf][nf][half * 2 + 0] + bias[n + 0];
                float vy = acc[mf][nf][half * 2 + 1] + bias[n + 1];
                uint32_t hw, lw;
                pack_hl(vx, vy, hw, lw);
                long long idx = ((long long)(b * NHEAD + h) * SEQ + s) * HDIM + d;
                *(uint32_t*)(dsth + idx) = hw;
                *(uint32_t*)(dstl + idx) = lw;
            }
        }
    }
}

// ---------------------------------------------------------------------------
// Attention, 512 threads, 256-row Q tile.  grid(8, 64).
// ---------------------------------------------------------------------------
// 128-row K/V tile with 512 threads (2 cp16 per thread)
__device__ __forceinline__ void cp_tile64_512(const __nv_bfloat16* __restrict__ src,
                                              uint32_t dst, int tid) {
#pragma unroll
    for (int i = 0; i < 2; i++) {
        int id = tid + i * 512;
        int r = id >> 3, c = id & 7;
        cp16(dst + r * LDA_B + c * 16, src + (long long)r * HDIM + c * 8);
    }
}
// 256-row Q tile with 512 threads (4 cp16 per thread)
__device__ __forceinline__ void cp_tileQ_512(const __nv_bfloat16* __restrict__ src,
                                             uint32_t dst, int tid) {
#pragma unroll
    for (int i = 0; i < 4; i++) {
        int id = tid + i * 512;
        int r = id >> 3, c = id & 7;
        cp16(dst + r * LDA_B + c * 16, src + (long long)r * HDIM + c * 8);
    }
}

// split S for one 16-col block: acc[0..3] cols +0..7, acc[4..7] cols +8..15
__device__ __forceinline__ void s_tile_nfp(float* acc,
                                           const uint32_t* FQh, const uint32_t* FQl,
                                           uint32_t kh, uint32_t kl, int nfp, int lane)
{
    const int r16 = lane & 15;
    const int koL = (lane >> 4) * 16;
    const uint32_t rowoff = (uint32_t)(nfp * 16 + r16) * LDA_B;
#pragma unroll
    for (int ks = 0; ks < 4; ks++) {
        uint32_t FBh[4], FBl[4];
        ldsm4(FBh, kh + rowoff + ks * 32 + koL);
        ldsm4(FBl, kl + rowoff + ks * 32 + koL);
        MMA_BF16(acc,     &FQh[4 * ks], FBh[0], FBh[2]);
        MMA_BF16(acc + 4, &FQh[4 * ks], FBh[1], FBh[3]);
        MMA_BF16(acc,     &FQh[4 * ks], FBl[0], FBl[2]);
        MMA_BF16(acc + 4, &FQh[4 * ks], FBl[1], FBl[3]);
        MMA_BF16(acc,     &FQl[4 * ks], FBh[0], FBh[2]);
        MMA_BF16(acc + 4, &FQl[4 * ks], FBh[1], FBh[3]);
    }
}

__global__ void __launch_bounds__(512, 1) attn(float* __restrict__ probs)
{
    extern __shared__ char sm[];
    const int tid = threadIdx.x, lane = tid & 31, w = tid >> 5;   // w: 0..15
    const int g = lane >> 2, tig = lane & 3;
    const int bh = blockIdx.y;
    const int m0 = blockIdx.x * 256;
    const uint32_t s0 = smem_u32(sm);

    const __nv_bfloat16* Qh = g_qh + ((long long)bh * SEQ + m0) * HDIM;
    const __nv_bfloat16* Ql = g_ql + ((long long)bh * SEQ + m0) * HDIM;
    const __nv_bfloat16* Kh = g_kh + (long long)bh * SEQ * HDIM;
    const __nv_bfloat16* Kl = g_kl + (long long)bh * SEQ * HDIM;
    const __nv_bfloat16* Vh = g_vh + (long long)bh * SEQ * HDIM;
    const __nv_bfloat16* Vl = g_vl + (long long)bh * SEQ * HDIM;
    float* C = probs + (long long)bh * SEQ * SEQ;

    // Q tile (group 0) then K tiles 0..2 into slots 0..2 (groups 1..3)
    cp_tileQ_512(Qh, s0 + OQH, tid);
    cp_tileQ_512(Ql, s0 + OQL, tid);
    CP_COMMIT;
#pragma unroll
    for (int t = 0; t < 3; t++) {
        uint32_t sl = s0 + OSLOT + t * SLOT_SZ;
        cp_tile64_512(Kh + (long long)t * 128 * HDIM, sl, tid);
        cp_tile64_512(Kl + (long long)t * 128 * HDIM, sl + KTILE, tid);
        CP_COMMIT;
    }
    CP_WAIT3;          // Q group done (3 K groups may be pending)
    __syncthreads();

    // Q fragments (constant)
    uint32_t FQh[16], FQl[16];
    {
        const uint32_t arow = (uint32_t)(w * 16 + (lane & 15)) * LDA_B;
        const uint32_t koL = (lane >> 4) * 16;
#pragma unroll
        for (int ks = 0; ks < 4; ks++) {
            ldsm4(&FQh[4 * ks], s0 + OQH + arow + ks * 32 + koL);
            ldsm4(&FQl[4 * ks], s0 + OQL + arow + ks * 32 + koL);
        }
    }

    // ---------------- pass A: row sums of exp(S), 4-stage K ring ----------
    float sum0 = 0.f, sum1 = 0.f;
    for (int j = 0; j < 16; j++) {
        if (j + 3 < 16) {
            uint32_t sl = s0 + OSLOT + ((j + 3) & 3) * SLOT_SZ;
            cp_tile64_512(Kh + (long long)(j + 3) * 128 * HDIM, sl, tid);
            cp_tile64_512(Kl + (long long)(j + 3) * 128 * HDIM, sl + KTILE, tid);
        }
        CP_COMMIT;      // possibly empty -> constant wait count
        CP_WAIT3;
        __syncthreads();
        const uint32_t kh = s0 + OSLOT + (j & 3) * SLOT_SZ;
        const uint32_t kl = kh + KTILE;
#pragma unroll
        for (int nfp = 0; nfp < 8; nfp++) {
            float acc[8] = {0.f, 0.f, 0.f, 0.f, 0.f, 0.f, 0.f, 0.f};
            s_tile_nfp(acc, FQh, FQl, kh, kl, nfp, lane);
            sum0 += __expf(acc[0]) + __expf(acc[1]) + __expf(acc[4]) + __expf(acc[5]);
            sum1 += __expf(acc[2]) + __expf(acc[3]) + __expf(acc[6]) + __expf(acc[7]);
        }
        __syncthreads();
    }
#pragma unroll
    for (int o = 1; o <= 2; o <<= 1) {
        sum0 += __shfl_xor_sync(0xffffffffu, sum0, o);
        sum1 += __shfl_xor_sync(0xffffffffu, sum1, o);
    }
    const float ri0 = 1.0f / sum0;
    const float ri1 = 1.0f / sum1;

    // ---------------- pass B: write P, accumulate ctx = P V ----------------
    // KV slots: slotB(i) = OSLOT + i*2*SLOT_SZ : Kh, Kl, Vh, Vl (18432 each)
    float ctx[8][4];
#pragma unroll
    for (int i = 0; i < 8; i++)
#pragma unroll
        for (int q = 0; q < 4; q++) ctx[i][q] = 0.f;

    {
        uint32_t sl = s0 + OSLOT;
        cp_tile64_512(Kh, sl, tid);
        cp_tile64_512(Kl, sl + KTILE, tid);
        cp_tile64_512(Vh, sl + 2 * KTILE, tid);
        cp_tile64_512(Vl, sl + 3 * KTILE, tid);
        CP_COMMIT;
    }

    const long long rowg = m0 + w * 16 + g;
    const uint32_t vlanerow = (uint32_t)((lane & 7) + ((lane >> 4) & 1) * 8) * LDA_B
                              + ((lane >> 3) & 1) * 16;

    for (int j = 0; j < 16; j++) {
        if (j + 1 < 16) {
            uint32_t sl = s0 + OSLOT + ((j + 1) & 1) * 2 * SLOT_SZ;
            cp_tile64_512(Kh + (long long)(j + 1) * 128 * HDIM, sl, tid);
            cp_tile64_512(Kl + (long long)(j + 1) * 128 * HDIM, sl + KTILE, tid);
            cp_tile64_512(Vh + (long long)(j + 1) * 128 * HDIM, sl + 2 * KTILE, tid);
            cp_tile64_512(Vl + (long long)(j + 1) * 128 * HDIM, sl + 3 * KTILE, tid);
        }
        CP_COMMIT;
        CP_WAIT1;
        __syncthreads();
        const uint32_t kh = s0 + OSLOT + (j & 1) * 2 * SLOT_SZ;
        const uint32_t kl = kh + KTILE;
        const uint32_t vh = kh + 2 * KTILE;
        const uint32_t vl = kh + 3 * KTILE;

#pragma unroll
        for (int nfp = 0; nfp < 8; nfp++) {
            float acc[8] = {0.f, 0.f, 0.f, 0.f, 0.f, 0.f, 0.f, 0.f};
            s_tile_nfp(acc, FQh, FQl, kh, kl, nfp, lane);
            float pE0 = __expf(acc[0]) * ri0, pE1 = __expf(acc[1]) * ri0;
            float pE2 = __expf(acc[2]) * ri1, pE3 = __expf(acc[3]) * ri1;
            float pO0 = __expf(acc[4]) * ri0, pO1 = __expf(acc[5]) * ri0;
            float pO2 = __expf(acc[6]) * ri1, pO3 = __expf(acc[7]) * ri1;
            float* Cr = C + rowg * SEQ + j * 128 + nfp * 16 + tig * 2;
            __stcs((float2*)Cr,                 make_float2(pE0, pE1));
            __stcs((float2*)(Cr + 8),           make_float2(pO0, pO1));
            __stcs((float2*)(Cr + 8 * SEQ),     make_float2(pE2, pE3));
            __stcs((float2*)(Cr + 8 * SEQ + 8), make_float2(pO2, pO3));
            uint32_t PAh[4], PAl[4];
            pack_hl(pE0, pE1, PAh[0], PAl[0]);
            pack_hl(pE2, pE3, PAh[1], PAl[1]);
            pack_hl(pO0, pO1, PAh[2], PAl[2]);
            pack_hl(pO2, pO3, PAh[3], PAl[3]);
            const uint32_t vbase = (uint32_t)(nfp * 16) * LDA_B + vlanerow;
#pragma unroll
            for (int gd = 0; gd < 4; gd++) {
                uint32_t FVh[4], FVl[4];
                ldsm4t(FVh, vh + vbase + gd * 32);
                ldsm4t(FVl, vl + vbase + gd * 32);
                MMA_BF16(ctx[2 * gd + 0], PAh, FVh[0], FVh[2]);
                MMA_BF16(ctx[2 * gd + 0], PAh, FVl[0], FVl[2]);
                MMA_BF16(ctx[2 * gd + 0], PAl, FVh[0], FVh[2]);
                MMA_BF16(ctx[2 * gd + 1], PAh, FVh[1], FVh[3]);
                MMA_BF16(ctx[2 * gd + 1], PAh, FVl[1], FVl[3]);
                MMA_BF16(ctx[2 * gd + 1], PAl, FVh[1], FVh[3]);
            }
        }
        __syncthreads();
    }

    // ctx epilogue -> bf16 hi/lo [b][s][h*64+d]
    const int b = bh >> 4, h = bh & 15;
    const int s = m0 + w * 16 + g;
    const long long base = ((long long)(b * SEQ + s)) * HID + h * HDIM;
#pragma unroll
    for (int dnf = 0; dnf < 8; dnf++) {
        const int d = dnf * 8 + tig * 2;
        uint32_t hw, lw;
        pack_hl(ctx[dnf][0], ctx[dnf][1], hw, lw);
        *(uint32_t*)(g_ch + base + d) = hw;
        *(uint32_t*)(g_cl + base + d) = lw;
        pack_hl(ctx[dnf][2], ctx[dnf][3], hw, lw);
        *(uint32_t*)(g_ch + base + 8LL * HID + d) = hw;
        *(uint32_t*)(g_cl + base + 8LL * HID + d) = lw;
    }
}

// ---------------------------------------------------------------------------
// Output projection + residual.  grid(8, 64), 256 thr.
// ---------------------------------------------------------------------------
__global__ void __launch_bounds__(256, 2) mm_out(
    const float* __restrict__ bo, const float* __restrict__ hidden,
    float* __restrict__ out)
{
    extern __shared__ char sm[];
    const int tid = threadIdx.x, lane = tid & 31, wid = tid >> 5;
    const int mw = wid >> 2, nw = wid & 3;
    const int m0 = blockIdx.y * 128, n0 = blockIdx.x * 128;
    const __nv_bfloat16* Ah = g_ch + (long long)m0 * HID;
    const __nv_bfloat16* Al = g_cl + (long long)m0 * HID;
    const __nv_bfloat16* Bh = g_wh + 3LL * HID * HID + (long long)n0 * HID;
    const __nv_bfloat16* Bl = g_wl + 3LL * HID * HID + (long long)n0 * HID;
    const uint32_t s0 = smem_u32(sm);

    float acc[4][4][4];
#pragma unroll
    for (int i = 0; i < 4; i++)
#pragma unroll
        for (int j = 0; j < 4; j++)
#pragma unroll
            for (int q = 0; q < 4; q++) acc[i][j][q] = 0.f;

    cp_tile32(Ah, s0 + 0 * TILE_B, tid);
    cp_tile32(Al, s0 + 1 * TILE_B, tid);
    cp_tile32(Bh, s0 + 2 * TILE_B, tid);
    cp_tile32(Bl, s0 + 3 * TILE_B, tid);
    CP_COMMIT;

    for (int c = 0; c < 32; c++) {
        if (c + 1 < 32) {
            uint32_t nb = s0 + ((c + 1) & 1) * GBUF;
            cp_tile32(Ah + (c + 1) * 32, nb + 0 * TILE_B, tid);
            cp_tile32(Al + (c + 1) * 32, nb + 1 * TILE_B, tid);
            cp_tile32(Bh + (c + 1) * 32, nb + 2 * TILE_B, tid);
            cp_tile32(Bl + (c + 1) * 32, nb + 3 * TILE_B, tid);
            CP_COMMIT;
            CP_WAIT1;
        } else {
            CP_WAIT0;
        }
        __syncthreads();
        uint32_t buf = s0 + (c & 1) * GBUF;
        mma_chunk<4, 4>(acc, buf, buf + TILE_B, buf + 2 * TILE_B, buf + 3 * TILE_B,
                        mw * 64, nw * 32, lane);
        __syncthreads();
    }

    const int g = lane >> 2, tig = lane & 3;
#pragma unroll
    for (int mf = 0; mf < 4; mf++) {
#pragma unroll
        for (int half = 0; half < 2; half++) {
            const long long m = m0 + mw * 64 + mf * 16 + g + half * 8;
#pragma unroll
            for (int nf = 0; nf < 4; nf++) {
                const int n = n0 + nw * 32 + nf * 8 + tig * 2;
                float2 hd = *(const float2*)(hidden + m * HID + n);
                float2 st;
                st.x = acc[mf][nf][half * 2 + 0] + bo[n + 0] + hd.x;
                st.y = acc[mf][nf][half * 2 + 1] + bo[n + 1] + hd.y;
                *(float2*)(out + m * HID + n) = st;
            }
        }
    }
}

// ---------------------------------------------------------------------------
extern "C" void kernel_launch(void* const* d_in, const int* in_sizes, int n_in,
                              void* d_out, int out_size)
{
    const float* X  = (const float*)d_in[0];
    const float* Wq = (const float*)d_in[1];
    const float* bq = (const float*)d_in[2];
    const float* Wk = (const float*)d_in[3];
    const float* bk = (const float*)d_in[4];
    const float* Wv = (const float*)d_in[5];
    const float* bv = (const float*)d_in[6];
    const float* Wo = (const float*)d_in[7];
    const float* bo = (const float*)d_in[8];

    float* out   = (float*)d_out;
    float* probs = out + OUT_ELEMS;

    cudaFuncSetAttribute(mm_qkv, cudaFuncAttributeMaxDynamicSharedMemorySize, SMEM_G);
    cudaFuncSetAttribute(mm_out, cudaFuncAttributeMaxDynamicSharedMemorySize, SMEM_G);
    cudaFuncSetAttribute(attn,   cudaFuncAttributeMaxDynamicSharedMemorySize, SMEM_ATTN);

    const long long NPREP = (long long)MROWS * HID + 4LL * HID * HID;
    prep<<<(unsigned)((NPREP + 255) / 256), 256>>>(X, Wq, Wk, Wv, Wo);
    mm_qkv<<<dim3(HID / 128, MROWS / 128, 3), 256, SMEM_G>>>(bq, bk, bv);
    attn<<<dim3(SEQ / 256, BATCH * NHEAD), 512, SMEM_ATTN>>>(probs);
    mm_out<<<dim3(HID / 128, MROWS / 128), 256, SMEM_G>>>(bo, X, out);
}

// round 8
// speedup vs baseline: 1.1474x; 1.1341x over previous
#include <cuda_runtime.h>
#include <cuda_fp16.h>
#include <cstdint>

// ---------------------------------------------------------------------------
constexpr int BATCH = 4;
constexpr int SEQ   = 2048;
constexpr int HID   = 1024;
constexpr int NHEAD = 16;
constexpr int HDIM  = 64;
constexpr int MROWS = BATCH * SEQ;                       // 8192
constexpr long long OUT_ELEMS = (long long)MROWS * HID;  // 8,388,608

// GEMM tiles: 32-col chunks, rows padded to 40 fp16 (80 B)
constexpr int LDT = 40;
constexpr int TILE_B = 128 * LDT * 2;     // 10240
constexpr int GBUF   = 4 * TILE_B;        // qkv: Ah,Al,Bh,Bl
constexpr int SMEM_G = 2 * GBUF;          // 81920
constexpr int GBUF2  = 3 * TILE_B;        // out: Ah,Bh,Bl
constexpr int SMEM_G2 = 2 * GBUF2;        // 61440

// Attention tiles: 64-col rows padded to 72 fp16 (144 B)
constexpr int LDA_B  = 144;
constexpr int KTILE  = 128 * LDA_B;       // 18432
constexpr int OQH = 0;
constexpr int OQL = 256 * LDA_B;          // 36864
constexpr int OSLOT = 2 * 256 * LDA_B;    // 73728: 4 slots x 36864
constexpr int SLOT_SZ = 2 * KTILE;        // 36864
constexpr int SMEM_ATTN = OSLOT + 4 * SLOT_SZ;  // 221184

// ---------------------------------------------------------------------------
// Prepped fp16 hi/lo operands
// ---------------------------------------------------------------------------
__device__ __half g_xh[MROWS * HID], g_xl[MROWS * HID];
__device__ __half g_wh[4 * HID * HID], g_wl[4 * HID * HID];
__device__ __half g_qh[64 * SEQ * HDIM], g_ql[64 * SEQ * HDIM];
__device__ __half g_kh[64 * SEQ * HDIM], g_kl[64 * SEQ * HDIM];
__device__ __half g_vh[64 * SEQ * HDIM], g_vl[64 * SEQ * HDIM];
__device__ __half g_ch[MROWS * HID];     // ctx: hi only

// ---------------------------------------------------------------------------
__device__ __forceinline__ uint32_t smem_u32(const void* p) {
    uint32_t a;
    asm("{ .reg .u64 t; cvta.to.shared.u64 t, %1; cvt.u32.u64 %0, t; }"
        : "=r"(a) : "l"(p));
    return a;
}

__device__ __forceinline__ void ldsm4(uint32_t* r, uint32_t a) {
    asm volatile("ldmatrix.sync.aligned.m8n8.x4.shared.b16 {%0,%1,%2,%3}, [%4];"
                 : "=r"(r[0]), "=r"(r[1]), "=r"(r[2]), "=r"(r[3]) : "r"(a));
}
__device__ __forceinline__ void ldsm4t(uint32_t* r, uint32_t a) {
    asm volatile("ldmatrix.sync.aligned.m8n8.x4.trans.shared.b16 {%0,%1,%2,%3}, [%4];"
                 : "=r"(r[0]), "=r"(r[1]), "=r"(r[2]), "=r"(r[3]) : "r"(a));
}

#define MMA_F16(d, a, b0, b1)                                               \
    asm volatile(                                                           \
        "mma.sync.aligned.m16n8k16.row.col.f32.f16.f16.f32 "                \
        "{%0,%1,%2,%3}, {%4,%5,%6,%7}, {%8,%9}, {%0,%1,%2,%3};"             \
        : "+f"((d)[0]), "+f"((d)[1]), "+f"((d)[2]), "+f"((d)[3])            \
        : "r"((a)[0]), "r"((a)[1]), "r"((a)[2]), "r"((a)[3]),               \
          "r"(b0), "r"(b1))

__device__ __forceinline__ void cp16(uint32_t dst, const void* src) {
    asm volatile("cp.async.cg.shared.global [%0], [%1], 16;" :: "r"(dst), "l"(src));
}
#define CP_COMMIT asm volatile("cp.async.commit_group;" ::: "memory")
#define CP_WAIT3  asm volatile("cp.async.wait_group 3;" ::: "memory")
#define CP_WAIT1  asm volatile("cp.async.wait_group 1;" ::: "memory")
#define CP_WAIT0  asm volatile("cp.async.wait_group 0;" ::: "memory")

__device__ __forceinline__ uint32_t pack2(float x, float y) {
    __half2 h = __floats2half2_rn(x, y);
    return *(uint32_t*)&h;
}

__device__ __forceinline__ void pack_hl(float x, float y, uint32_t& h, uint32_t& l) {
    __half hx = __float2half_rn(x);
    __half hy = __float2half_rn(y);
    __half lx = __float2half_rn(x - __half2float(hx));
    __half ly = __float2half_rn(y - __half2float(hy));
    h = ((uint32_t)__half_as_ushort(hy) << 16) | __half_as_ushort(hx);
    l = ((uint32_t)__half_as_ushort(ly) << 16) | __half_as_ushort(lx);
}

// ---------------------------------------------------------------------------
// prep: split X and the 4 weight matrices into fp16 hi/lo once.
// ---------------------------------------------------------------------------
__global__ void __launch_bounds__(256) prep(
    const float* __restrict__ X,  const float* __restrict__ Wq,
    const float* __restrict__ Wk, const float* __restrict__ Wv,
    const float* __restrict__ Wo)
{
    const long long NX = (long long)MROWS * HID;
    long long i = (long long)blockIdx.x * 256 + threadIdx.x;
    float v; __half *dh, *dl; long long o;
    if (i < NX) {
        v = X[i]; dh = g_xh; dl = g_xl; o = i;
    } else {
        long long j = i - NX;
        int w = (int)(j >> 20);
        long long r = j & 1048575;
        if (w == 0) v = Wq[r]; else if (w == 1) v = Wk[r];
        else if (w == 2) v = Wv[r]; else v = Wo[r];
        dh = g_wh; dl = g_wl; o = j;
    }
    __half hb = __float2half_rn(v);
    dh[o] = hb;
    dl[o] = __float2half_rn(v - __half2float(hb));
}

// ---------------------------------------------------------------------------
// 3-term split-fp16 warp MMA over one 32-wide K chunk (qkv).
// ---------------------------------------------------------------------------
template <int MF, int NF>
__device__ __forceinline__ void mma_chunk3(float (&acc)[MF][NF][4],
                                           uint32_t aHi, uint32_t aLo,
                                           uint32_t bHi, uint32_t bLo,
                                           int mbase, int nbase, int lane)
{
    const int r16 = lane & 15;
    const int koL = (lane >> 4) * 16;
#pragma unroll
    for (int ks = 0; ks < 2; ks++) {
        const int kb = ks * 32 + koL;
        uint32_t FA[4 * MF], FB[2 * NF], FC[2 * NF];
#pragma unroll
        for (int mf = 0; mf < MF; mf++)
            ldsm4(&FA[4 * mf], aHi + (mbase + mf * 16 + r16) * (LDT * 2) + kb);
#pragma unroll
        for (int nb = 0; nb < NF / 2; nb++)
            ldsm4(&FB[4 * nb], bHi + (nbase + nb * 16 + r16) * (LDT * 2) + kb);
#pragma unroll
        for (int mf = 0; mf < MF; mf++)
#pragma unroll
            for (int nf = 0; nf < NF; nf++)
                MMA_F16(acc[mf][nf], &FA[4 * mf],
                        FB[4 * (nf >> 1) + (nf & 1)], FB[4 * (nf >> 1) + 2 + (nf & 1)]);
#pragma unroll
        for (int nb = 0; nb < NF / 2; nb++)
            ldsm4(&FC[4 * nb], bLo + (nbase + nb * 16 + r16) * (LDT * 2) + kb);
#pragma unroll
        for (int mf = 0; mf < MF; mf++)
#pragma unroll
            for (int nf = 0; nf < NF; nf++)
                MMA_F16(acc[mf][nf], &FA[4 * mf],
                        FC[4 * (nf >> 1) + (nf & 1)], FC[4 * (nf >> 1) + 2 + (nf & 1)]);
#pragma unroll
        for (int mf = 0; mf < MF; mf++)
            ldsm4(&FA[4 * mf], aLo + (mbase + mf * 16 + r16) * (LDT * 2) + kb);
#pragma unroll
        for (int mf = 0; mf < MF; mf++)
#pragma unroll
            for (int nf = 0; nf < NF; nf++)
                MMA_F16(acc[mf][nf], &FA[4 * mf],
                        FB[4 * (nf >> 1) + (nf & 1)], FB[4 * (nf >> 1) + 2 + (nf & 1)]);
    }
}

// 2-term variant: A hi only, B hi+lo (out projection).
template <int MF, int NF>
__device__ __forceinline__ void mma_chunk2(float (&acc)[MF][NF][4],
                                           uint32_t aHi,
                                           uint32_t bHi, uint32_t bLo,
                                           int mbase, int nbase, int lane)
{
    const int r16 = lane & 15;
    const int koL = (lane >> 4) * 16;
#pragma unroll
    for (int ks = 0; ks < 2; ks++) {
        const int kb = ks * 32 + koL;
        uint32_t FA[4 * MF], FB[2 * NF];
#pragma unroll
        for (int mf = 0; mf < MF; mf++)
            ldsm4(&FA[4 * mf], aHi + (mbase + mf * 16 + r16) * (LDT * 2) + kb);
#pragma unroll
        for (int nb = 0; nb < NF / 2; nb++)
            ldsm4(&FB[4 * nb], bHi + (nbase + nb * 16 + r16) * (LDT * 2) + kb);
#pragma unroll
        for (int mf = 0; mf < MF; mf++)
#pragma unroll
            for (int nf = 0; nf < NF; nf++)
                MMA_F16(acc[mf][nf], &FA[4 * mf],
                        FB[4 * (nf >> 1) + (nf & 1)], FB[4 * (nf >> 1) + 2 + (nf & 1)]);
#pragma unroll
        for (int nb = 0; nb < NF / 2; nb++)
            ldsm4(&FB[4 * nb], bLo + (nbase + nb * 16 + r16) * (LDT * 2) + kb);
#pragma unroll
        for (int mf = 0; mf < MF; mf++)
#pragma unroll
            for (int nf = 0; nf < NF; nf++)
                MMA_F16(acc[mf][nf], &FA[4 * mf],
                        FB[4 * (nf >> 1) + (nf & 1)], FB[4 * (nf >> 1) + 2 + (nf & 1)]);
    }
}

// cp.async a 128x32 fp16 tile (ld = HID) into LDT=40 smem (256 thr)
__device__ __forceinline__ void cp_tile32(const __half* __restrict__ src,
                                          uint32_t dst, int tid) {
#pragma unroll
    for (int i = 0; i < 2; i++) {
        int id = tid + i * 256;
        int r = id >> 2, c = id & 3;
        cp16(dst + r * (LDT * 2) + c * 16, src + (long long)r * HID + c * 8);
    }
}

// ---------------------------------------------------------------------------
// QKV projection (3-term).  grid(8, 64, 3), 256 thr.
// ---------------------------------------------------------------------------
__global__ void __launch_bounds__(256, 2) mm_qkv(
    const float* __restrict__ bq, const float* __restrict__ bk,
    const float* __restrict__ bv)
{
    extern __shared__ char sm[];
    const int z = blockIdx.z;
    const float* bias = (z == 0) ? bq : (z == 1) ? bk : bv;
    __half* dsth = (z == 0) ? g_qh : (z == 1) ? g_kh : g_vh;
    __half* dstl = (z == 0) ? g_ql : (z == 1) ? g_kl : g_vl;

    const int tid = threadIdx.x, lane = tid & 31, wid = tid >> 5;
    const int mw = wid >> 2, nw = wid & 3;
    const int m0 = blockIdx.y * 128, n0 = blockIdx.x * 128;
    const __half* Ah = g_xh + (long long)m0 * HID;
    const __half* Al = g_xl + (long long)m0 * HID;
    const __half* Bh = g_wh + (long long)z * HID * HID + (long long)n0 * HID;
    const __half* Bl = g_wl + (long long)z * HID * HID + (long long)n0 * HID;
    const uint32_t s0 = smem_u32(sm);

    float acc[4][4][4];
#pragma unroll
    for (int i = 0; i < 4; i++)
#pragma unroll
        for (int j = 0; j < 4; j++)
#pragma unroll
            for (int q = 0; q < 4; q++) acc[i][j][q] = 0.f;

    cp_tile32(Ah, s0 + 0 * TILE_B, tid);
    cp_tile32(Al, s0 + 1 * TILE_B, tid);
    cp_tile32(Bh, s0 + 2 * TILE_B, tid);
    cp_tile32(Bl, s0 + 3 * TILE_B, tid);
    CP_COMMIT;

    for (int c = 0; c < 32; c++) {
        if (c + 1 < 32) {
            uint32_t nb = s0 + ((c + 1) & 1) * GBUF;
            cp_tile32(Ah + (c + 1) * 32, nb + 0 * TILE_B, tid);
            cp_tile32(Al + (c + 1) * 32, nb + 1 * TILE_B, tid);
            cp_tile32(Bh + (c + 1) * 32, nb + 2 * TILE_B, tid);
            cp_tile32(Bl + (c + 1) * 32, nb + 3 * TILE_B, tid);
            CP_COMMIT;
            CP_WAIT1;
        } else {
            CP_WAIT0;
        }
        __syncthreads();
        uint32_t buf = s0 + (c & 1) * GBUF;
        mma_chunk3<4, 4>(acc, buf, buf + TILE_B, buf + 2 * TILE_B, buf + 3 * TILE_B,
                         mw * 64, nw * 32, lane);
        __syncthreads();
    }

    const int g = lane >> 2, tig = lane & 3;
#pragma unroll
    for (int mf = 0; mf < 4; mf++) {
#pragma unroll
        for (int half = 0; half < 2; half++) {
            const int m = m0 + mw * 64 + mf * 16 + g + half * 8;
            const int b = m >> 11, s = m & 2047;
#pragma unroll
            for (int nf = 0; nf < 4; nf++) {
                const int n = n0 + nw * 32 + nf * 8 + tig * 2;
                const int h = n >> 6, d = n & 63;
                float vx = acc[mf][nf][half * 2 + 0] + bias[n + 0];
                float vy = acc[mf][nf][half * 2 + 1] + bias[n + 1];
                uint32_t hw, lw;
                pack_hl(vx, vy, hw, lw);
                long long idx = ((long long)(b * NHEAD + h) * SEQ + s) * HDIM + d;
                *(uint32_t*)(dsth + idx) = hw;
                *(uint32_t*)(dstl + idx) = lw;
            }
        }
    }
}

// ---------------------------------------------------------------------------
// Attention, 512 threads, 256-row Q tile.  grid(8, 64).
// ---------------------------------------------------------------------------
__device__ __forceinline__ void cp_tile64_512(const __half* __restrict__ src,
                                              uint32_t dst, int tid) {
#pragma unroll
    for (int i = 0; i < 2; i++) {
        int id = tid + i * 512;
        int r = id >> 3, c = id & 7;
        cp16(dst + r * LDA_B + c * 16, src + (long long)r * HDIM + c * 8);
    }
}
__device__ __forceinline__ void cp_tileQ_512(const __half* __restrict__ src,
                                             uint32_t dst, int tid) {
#pragma unroll
    for (int i = 0; i < 4; i++) {
        int id = tid + i * 512;
        int r = id >> 3, c = id & 7;
        cp16(dst + r * LDA_B + c * 16, src + (long long)r * HDIM + c * 8);
    }
}

// 3-term S tile: Qh*Kh + Qh*Kl + Ql*Kh   (pass B)
__device__ __forceinline__ void s_tile3(float* acc,
                                        const uint32_t* FQh, const uint32_t* FQl,
                                        uint32_t kh, uint32_t kl, int nfp, int lane)
{
    const int r16 = lane & 15;
    const int koL = (lane >> 4) * 16;
    const uint32_t rowoff = (uint32_t)(nfp * 16 + r16) * LDA_B;
#pragma unroll
    for (int ks = 0; ks < 4; ks++) {
        uint32_t FBh[4], FBl[4];
        ldsm4(FBh, kh + rowoff + ks * 32 + koL);
        ldsm4(FBl, kl + rowoff + ks * 32 + koL);
        MMA_F16(acc,     &FQh[4 * ks], FBh[0], FBh[2]);
        MMA_F16(acc + 4, &FQh[4 * ks], FBh[1], FBh[3]);
        MMA_F16(acc,     &FQh[4 * ks], FBl[0], FBl[2]);
        MMA_F16(acc + 4, &FQh[4 * ks], FBl[1], FBl[3]);
        MMA_F16(acc,     &FQl[4 * ks], FBh[0], FBh[2]);
        MMA_F16(acc + 4, &FQl[4 * ks], FBh[1], FBh[3]);
    }
}

// 2-term S tile for pass A sums: Qh*Kh + Ql*Kh  (drops Qh*Kl; Kl_j independent
// across columns j, so its effect on the row sum averages out)
__device__ __forceinline__ void s_tile2(float* acc,
                                        const uint32_t* FQh, const uint32_t* FQl,
                                        uint32_t kh, int nfp, int lane)
{
    const int r16 = lane & 15;
    const int koL = (lane >> 4) * 16;
    const uint32_t rowoff = (uint32_t)(nfp * 16 + r16) * LDA_B;
#pragma unroll
    for (int ks = 0; ks < 4; ks++) {
        uint32_t FBh[4];
        ldsm4(FBh, kh + rowoff + ks * 32 + koL);
        MMA_F16(acc,     &FQh[4 * ks], FBh[0], FBh[2]);
        MMA_F16(acc + 4, &FQh[4 * ks], FBh[1], FBh[3]);
        MMA_F16(acc,     &FQl[4 * ks], FBh[0], FBh[2]);
        MMA_F16(acc + 4, &FQl[4 * ks], FBh[1], FBh[3]);
    }
}

__global__ void __launch_bounds__(512, 1) attn(float* __restrict__ probs)
{
    extern __shared__ char sm[];
    const int tid = threadIdx.x, lane = tid & 31, w = tid >> 5;
    const int g = lane >> 2, tig = lane & 3;
    const int bh = blockIdx.y;
    const int m0 = blockIdx.x * 256;
    const uint32_t s0 = smem_u32(sm);

    const __half* Qh = g_qh + ((long long)bh * SEQ + m0) * HDIM;
    const __half* Ql = g_ql + ((long long)bh * SEQ + m0) * HDIM;
    const __half* Kh = g_kh + (long long)bh * SEQ * HDIM;
    const __half* Kl = g_kl + (long long)bh * SEQ * HDIM;
    const __half* Vh = g_vh + (long long)bh * SEQ * HDIM;
    const __half* Vl = g_vl + (long long)bh * SEQ * HDIM;
    float* C = probs + (long long)bh * SEQ * SEQ;

    // Q tile (group 0) then K-hi tiles 0..2 into slots 0..2 (pass A needs Kh only)
    cp_tileQ_512(Qh, s0 + OQH, tid);
    cp_tileQ_512(Ql, s0 + OQL, tid);
    CP_COMMIT;
#pragma unroll
    for (int t = 0; t < 3; t++) {
        uint32_t sl = s0 + OSLOT + t * SLOT_SZ;
        cp_tile64_512(Kh + (long long)t * 128 * HDIM, sl, tid);
        CP_COMMIT;
    }
    CP_WAIT3;
    __syncthreads();

    uint32_t FQh[16], FQl[16];
    {
        const uint32_t arow = (uint32_t)(w * 16 + (lane & 15)) * LDA_B;
        const uint32_t koL = (lane >> 4) * 16;
#pragma unroll
        for (int ks = 0; ks < 4; ks++) {
            ldsm4(&FQh[4 * ks], s0 + OQH + arow + ks * 32 + koL);
            ldsm4(&FQl[4 * ks], s0 + OQL + arow + ks * 32 + koL);
        }
    }

    // ---------------- pass A: row sums of exp(S2), 4-stage Kh ring ---------
    float sum0 = 0.f, sum1 = 0.f;
    for (int j = 0; j < 16; j++) {
        if (j + 3 < 16) {
            uint32_t sl = s0 + OSLOT + ((j + 3) & 3) * SLOT_SZ;
            cp_tile64_512(Kh + (long long)(j + 3) * 128 * HDIM, sl, tid);
        }
        CP_COMMIT;
        CP_WAIT3;
        __syncthreads();
        const uint32_t kh = s0 + OSLOT + (j & 3) * SLOT_SZ;
#pragma unroll
        for (int nfp = 0; nfp < 8; nfp++) {
            float acc[8] = {0.f, 0.f, 0.f, 0.f, 0.f, 0.f, 0.f, 0.f};
            s_tile2(acc, FQh, FQl, kh, nfp, lane);
            sum0 += __expf(acc[0]) + __expf(acc[1]) + __expf(acc[4]) + __expf(acc[5]);
            sum1 += __expf(acc[2]) + __expf(acc[3]) + __expf(acc[6]) + __expf(acc[7]);
        }
        __syncthreads();
    }
#pragma unroll
    for (int o = 1; o <= 2; o <<= 1) {
        sum0 += __shfl_xor_sync(0xffffffffu, sum0, o);
        sum1 += __shfl_xor_sync(0xffffffffu, sum1, o);
    }
    const float ri0 = 1.0f / sum0;
    const float ri1 = 1.0f / sum1;

    // ---------------- pass B: write P (3-term S), ctx = Ph (Vh+Vl) --------
    float ctx[8][4];
#pragma unroll
    for (int i = 0; i < 8; i++)
#pragma unroll
        for (int q = 0; q < 4; q++) ctx[i][q] = 0.f;

    {
        uint32_t sl = s0 + OSLOT;
        cp_tile64_512(Kh, sl, tid);
        cp_tile64_512(Kl, sl + KTILE, tid);
        cp_tile64_512(Vh, sl + 2 * KTILE, tid);
        cp_tile64_512(Vl, sl + 3 * KTILE, tid);
        CP_COMMIT;
    }

    const long long rowg = m0 + w * 16 + g;
    const uint32_t vlanerow = (uint32_t)((lane & 7) + ((lane >> 4) & 1) * 8) * LDA_B
                              + ((lane >> 3) & 1) * 16;

    for (int j = 0; j < 16; j++) {
        if (j + 1 < 16) {
            uint32_t sl = s0 + OSLOT + ((j + 1) & 1) * 2 * SLOT_SZ;
            cp_tile64_512(Kh + (long long)(j + 1) * 128 * HDIM, sl, tid);
            cp_tile64_512(Kl + (long long)(j + 1) * 128 * HDIM, sl + KTILE, tid);
            cp_tile64_512(Vh + (long long)(j + 1) * 128 * HDIM, sl + 2 * KTILE, tid);
            cp_tile64_512(Vl + (long long)(j + 1) * 128 * HDIM, sl + 3 * KTILE, tid);
        }
        CP_COMMIT;
        CP_WAIT1;
        __syncthreads();
        const uint32_t kh = s0 + OSLOT + (j & 1) * 2 * SLOT_SZ;
        const uint32_t kl = kh + KTILE;
        const uint32_t vh = kh + 2 * KTILE;
        const uint32_t vl = kh + 3 * KTILE;

#pragma unroll
        for (int nfp = 0; nfp < 8; nfp++) {
            float acc[8] = {0.f, 0.f, 0.f, 0.f, 0.f, 0.f, 0.f, 0.f};
            s_tile3(acc, FQh, FQl, kh, kl, nfp, lane);
            float pE0 = __expf(acc[0]) * ri0, pE1 = __expf(acc[1]) * ri0;
            float pE2 = __expf(acc[2]) * ri1, pE3 = __expf(acc[3]) * ri1;
            float pO0 = __expf(acc[4]) * ri0, pO1 = __expf(acc[5]) * ri0;
            float pO2 = __expf(acc[6]) * ri1, pO3 = __expf(acc[7]) * ri1;
            float* Cr = C + rowg * SEQ + j * 128 + nfp * 16 + tig * 2;
            __stcs((float2*)Cr,                 make_float2(pE0, pE1));
            __stcs((float2*)(Cr + 8),           make_float2(pO0, pO1));
            __stcs((float2*)(Cr + 8 * SEQ),     make_float2(pE2, pE3));
            __stcs((float2*)(Cr + 8 * SEQ + 8), make_float2(pO2, pO3));
            uint32_t PAh[4];
            PAh[0] = pack2(pE0, pE1);
            PAh[1] = pack2(pE2, pE3);
            PAh[2] = pack2(pO0, pO1);
            PAh[3] = pack2(pO2, pO3);
            const uint32_t vbase = (uint32_t)(nfp * 16) * LDA_B + vlanerow;
#pragma unroll
            for (int gd = 0; gd < 4; gd++) {
                uint32_t FVh[4], FVl[4];
                ldsm4t(FVh, vh + vbase + gd * 32);
                ldsm4t(FVl, vl + vbase + gd * 32);
                MMA_F16(ctx[2 * gd + 0], PAh, FVh[0], FVh[2]);
                MMA_F16(ctx[2 * gd + 0], PAh, FVl[0], FVl[2]);
                MMA_F16(ctx[2 * gd + 1], PAh, FVh[1], FVh[3]);
                MMA_F16(ctx[2 * gd + 1], PAh, FVl[1], FVl[3]);
            }
        }
        __syncthreads();
    }

    // ctx epilogue -> fp16 (hi only) [b][s][h*64+d]
    const int b = bh >> 4, h = bh & 15;
    const int s = m0 + w * 16 + g;
    const long long base = ((long long)(b * SEQ + s)) * HID + h * HDIM;
#pragma unroll
    for (int dnf = 0; dnf < 8; dnf++) {
        const int d = dnf * 8 + tig * 2;
        *(uint32_t*)(g_ch + base + d) = pack2(ctx[dnf][0], ctx[dnf][1]);
        *(uint32_t*)(g_ch + base + 8LL * HID + d) = pack2(ctx[dnf][2], ctx[dnf][3]);
    }
}

// ---------------------------------------------------------------------------
// Output projection + residual (2-term).  grid(8, 64), 256 thr.
// ---------------------------------------------------------------------------
__global__ void __launch_bounds__(256, 2) mm_out(
    const float* __restrict__ bo, const float* __restrict__ hidden,
    float* __restrict__ out)
{
    extern __shared__ char sm[];
    const int tid = threadIdx.x, lane = tid & 31, wid = tid >> 5;
    const int mw = wid >> 2, nw = wid & 3;
    const int m0 = blockIdx.y * 128, n0 = blockIdx.x * 128;
    const __half* Ah = g_ch + (long long)m0 * HID;
    const __half* Bh = g_wh + 3LL * HID * HID + (long long)n0 * HID;
    const __half* Bl = g_wl + 3LL * HID * HID + (long long)n0 * HID;
    const uint32_t s0 = smem_u32(sm);

    float acc[4][4][4];
#pragma unroll
    for (int i = 0; i < 4; i++)
#pragma unroll
        for (int j = 0; j < 4; j++)
#pragma unroll
            for (int q = 0; q < 4; q++) acc[i][j][q] = 0.f;

    cp_tile32(Ah, s0 + 0 * TILE_B, tid);
    cp_tile32(Bh, s0 + 1 * TILE_B, tid);
    cp_tile32(Bl, s0 + 2 * TILE_B, tid);
    CP_COMMIT;

    for (int c = 0; c < 32; c++) {
        if (c + 1 < 32) {
            uint32_t nb = s0 + ((c + 1) & 1) * GBUF2;
            cp_tile32(Ah + (c + 1) * 32, nb + 0 * TILE_B, tid);
            cp_tile32(Bh + (c + 1) * 32, nb + 1 * TILE_B, tid);
            cp_tile32(Bl + (c + 1) * 32, nb + 2 * TILE_B, tid);
            CP_COMMIT;
            CP_WAIT1;
        } else {
            CP_WAIT0;
        }
        __syncthreads();
        uint32_t buf = s0 + (c & 1) * GBUF2;
        mma_chunk2<4, 4>(acc, buf, buf + TILE_B, buf + 2 * TILE_B,
                         mw * 64, nw * 32, lane);
        __syncthreads();
    }

    const int g = lane >> 2, tig = lane & 3;
#pragma unroll
    for (int mf = 0; mf < 4; mf++) {
#pragma unroll
        for (int half = 0; half < 2; half++) {
            const long long m = m0 + mw * 64 + mf * 16 + g + half * 8;
#pragma unroll
            for (int nf = 0; nf < 4; nf++) {
                const int n = n0 + nw * 32 + nf * 8 + tig * 2;
                float2 hd = *(const float2*)(hidden + m * HID + n);
                float2 st;
                st.x = acc[mf][nf][half * 2 + 0] + bo[n + 0] + hd.x;
                st.y = acc[mf][nf][half * 2 + 1] + bo[n + 1] + hd.y;
                *(float2*)(out + m * HID + n) = st;
            }
        }
    }
}

// ---------------------------------------------------------------------------
extern "C" void kernel_launch(void* const* d_in, const int* in_sizes, int n_in,
                              void* d_out, int out_size)
{
    const float* X  = (const float*)d_in[0];
    const float* Wq = (const float*)d_in[1];
    const float* bq = (const float*)d_in[2];
    const float* Wk = (const float*)d_in[3];
    const float* bk = (const float*)d_in[4];
    const float* Wv = (const float*)d_in[5];
    const float* bv = (const float*)d_in[6];
    const float* Wo = (const float*)d_in[7];
    const float* bo = (const float*)d_in[8];

    float* out   = (float*)d_out;
    float* probs = out + OUT_ELEMS;

    cudaFuncSetAttribute(mm_qkv, cudaFuncAttributeMaxDynamicSharedMemorySize, SMEM_G);
    cudaFuncSetAttribute(mm_out, cudaFuncAttributeMaxDynamicSharedMemorySize, SMEM_G2);
    cudaFuncSetAttribute(attn,   cudaFuncAttributeMaxDynamicSharedMemorySize, SMEM_ATTN);

    const long long NPREP = (long long)MROWS * HID + 4LL * HID * HID;
    prep<<<(unsigned)((NPREP + 255) / 256), 256>>>(X, Wq, Wk, Wv, Wo);
    mm_qkv<<<dim3(HID / 128, MROWS / 128, 3), 256, SMEM_G>>>(bq, bk, bv);
    attn<<<dim3(SEQ / 256, BATCH * NHEAD), 512, SMEM_ATTN>>>(probs);
    mm_out<<<dim3(HID / 128, MROWS / 128), 256, SMEM_G2>>>(bo, X, out);
}

// round 9
// speedup vs baseline: 1.2363x; 1.0775x over previous
#include <cuda_runtime.h>
#include <cuda_fp16.h>
#include <cstdint>

// ---------------------------------------------------------------------------
constexpr int BATCH = 4;
constexpr int SEQ   = 2048;
constexpr int HID   = 1024;
constexpr int NHEAD = 16;
constexpr int HDIM  = 64;
constexpr int MROWS = BATCH * SEQ;                       // 8192
constexpr long long OUT_ELEMS = (long long)MROWS * HID;  // 8,388,608

// GEMM tiles: 32-col chunks, rows padded to 40 fp16 (80 B)
constexpr int LDT = 40;
constexpr int TILE_B = 128 * LDT * 2;     // 10240
constexpr int GBUF   = 4 * TILE_B;        // qkv: Ah,Al,Bh,Bl
constexpr int SMEM_G = 2 * GBUF;          // 81920
constexpr int GBUF2  = 3 * TILE_B;        // out: Ah,Bh,Bl
constexpr int SMEM_G2 = 2 * GBUF2;        // 61440

// Attention tiles: 64-col rows padded to 72 fp16 (144 B)
constexpr int LDA_B  = 144;
constexpr int QTILE  = 128 * LDA_B;       // 18432 (128-row Q component)
constexpr int KT64   = 64 * LDA_B;        // 9216  (64-row K/V tile)
constexpr int OQH = 0;
constexpr int OQL = QTILE;                // 18432
constexpr int OSLOT = 2 * QTILE;          // 36864
// pass A: 4 ring slots of KT64 at OSLOT (36864..73728)
// pass B: 2 stages x (Kh,Kl,Vh,Vl) = 2 x 4 x 9216 at OSLOT (36864..110592)
constexpr int BSTAGE = 4 * KT64;          // 36864
constexpr int SMEM_ATTN = OSLOT + 2 * BSTAGE;   // 110592  (2 CTAs/SM)

// ---------------------------------------------------------------------------
// Prepped fp16 hi/lo operands
// ---------------------------------------------------------------------------
__device__ __half g_xh[MROWS * HID], g_xl[MROWS * HID];
__device__ __half g_wh[4 * HID * HID], g_wl[4 * HID * HID];
__device__ __half g_qh[64 * SEQ * HDIM], g_ql[64 * SEQ * HDIM];
__device__ __half g_kh[64 * SEQ * HDIM], g_kl[64 * SEQ * HDIM];
__device__ __half g_vh[64 * SEQ * HDIM], g_vl[64 * SEQ * HDIM];
__device__ __half g_ch[MROWS * HID];     // ctx: hi only

// ---------------------------------------------------------------------------
__device__ __forceinline__ uint32_t smem_u32(const void* p) {
    uint32_t a;
    asm("{ .reg .u64 t; cvta.to.shared.u64 t, %1; cvt.u32.u64 %0, t; }"
        : "=r"(a) : "l"(p));
    return a;
}

__device__ __forceinline__ void ldsm4(uint32_t* r, uint32_t a) {
    asm volatile("ldmatrix.sync.aligned.m8n8.x4.shared.b16 {%0,%1,%2,%3}, [%4];"
                 : "=r"(r[0]), "=r"(r[1]), "=r"(r[2]), "=r"(r[3]) : "r"(a));
}
__device__ __forceinline__ void ldsm4t(uint32_t* r, uint32_t a) {
    asm volatile("ldmatrix.sync.aligned.m8n8.x4.trans.shared.b16 {%0,%1,%2,%3}, [%4];"
                 : "=r"(r[0]), "=r"(r[1]), "=r"(r[2]), "=r"(r[3]) : "r"(a));
}

#define MMA_F16(d, a, b0, b1)                                               \
    asm volatile(                                                           \
        "mma.sync.aligned.m16n8k16.row.col.f32.f16.f16.f32 "                \
        "{%0,%1,%2,%3}, {%4,%5,%6,%7}, {%8,%9}, {%0,%1,%2,%3};"             \
        : "+f"((d)[0]), "+f"((d)[1]), "+f"((d)[2]), "+f"((d)[3])            \
        : "r"((a)[0]), "r"((a)[1]), "r"((a)[2]), "r"((a)[3]),               \
          "r"(b0), "r"(b1))

__device__ __forceinline__ void cp16(uint32_t dst, const void* src) {
    asm volatile("cp.async.cg.shared.global [%0], [%1], 16;" :: "r"(dst), "l"(src));
}
#define CP_COMMIT asm volatile("cp.async.commit_group;" ::: "memory")
#define CP_WAIT3  asm volatile("cp.async.wait_group 3;" ::: "memory")
#define CP_WAIT1  asm volatile("cp.async.wait_group 1;" ::: "memory")
#define CP_WAIT0  asm volatile("cp.async.wait_group 0;" ::: "memory")

__device__ __forceinline__ uint32_t pack2(float x, float y) {
    __half2 h = __floats2half2_rn(x, y);
    return *(uint32_t*)&h;
}

__device__ __forceinline__ void pack_hl(float x, float y, uint32_t& h, uint32_t& l) {
    __half hx = __float2half_rn(x);
    __half hy = __float2half_rn(y);
    __half lx = __float2half_rn(x - __half2float(hx));
    __half ly = __float2half_rn(y - __half2float(hy));
    h = ((uint32_t)__half_as_ushort(hy) << 16) | __half_as_ushort(hx);
    l = ((uint32_t)__half_as_ushort(ly) << 16) | __half_as_ushort(lx);
}

// ---------------------------------------------------------------------------
// prep: split X and the 4 weight matrices into fp16 hi/lo once.
// ---------------------------------------------------------------------------
__global__ void __launch_bounds__(256) prep(
    const float* __restrict__ X,  const float* __restrict__ Wq,
    const float* __restrict__ Wk, const float* __restrict__ Wv,
    const float* __restrict__ Wo)
{
    const long long NX = (long long)MROWS * HID;
    long long i = (long long)blockIdx.x * 256 + threadIdx.x;
    float v; __half *dh, *dl; long long o;
    if (i < NX) {
        v = X[i]; dh = g_xh; dl = g_xl; o = i;
    } else {
        long long j = i - NX;
        int w = (int)(j >> 20);
        long long r = j & 1048575;
        if (w == 0) v = Wq[r]; else if (w == 1) v = Wk[r];
        else if (w == 2) v = Wv[r]; else v = Wo[r];
        dh = g_wh; dl = g_wl; o = j;
    }
    __half hb = __float2half_rn(v);
    dh[o] = hb;
    dl[o] = __float2half_rn(v - __half2float(hb));
}

// ---------------------------------------------------------------------------
// 3-term split-fp16 warp MMA over one 32-wide K chunk (qkv).
// ---------------------------------------------------------------------------
template <int MF, int NF>
__device__ __forceinline__ void mma_chunk3(float (&acc)[MF][NF][4],
                                           uint32_t aHi, uint32_t aLo,
                                           uint32_t bHi, uint32_t bLo,
                                           int mbase, int nbase, int lane)
{
    const int r16 = lane & 15;
    const int koL = (lane >> 4) * 16;
#pragma unroll
    for (int ks = 0; ks < 2; ks++) {
        const int kb = ks * 32 + koL;
        uint32_t FA[4 * MF], FB[2 * NF], FC[2 * NF];
#pragma unroll
        for (int mf = 0; mf < MF; mf++)
            ldsm4(&FA[4 * mf], aHi + (mbase + mf * 16 + r16) * (LDT * 2) + kb);
#pragma unroll
        for (int nb = 0; nb < NF / 2; nb++)
            ldsm4(&FB[4 * nb], bHi + (nbase + nb * 16 + r16) * (LDT * 2) + kb);
#pragma unroll
        for (int mf = 0; mf < MF; mf++)
#pragma unroll
            for (int nf = 0; nf < NF; nf++)
                MMA_F16(acc[mf][nf], &FA[4 * mf],
                        FB[4 * (nf >> 1) + (nf & 1)], FB[4 * (nf >> 1) + 2 + (nf & 1)]);
#pragma unroll
        for (int nb = 0; nb < NF / 2; nb++)
            ldsm4(&FC[4 * nb], bLo + (nbase + nb * 16 + r16) * (LDT * 2) + kb);
#pragma unroll
        for (int mf = 0; mf < MF; mf++)
#pragma unroll
            for (int nf = 0; nf < NF; nf++)
                MMA_F16(acc[mf][nf], &FA[4 * mf],
                        FC[4 * (nf >> 1) + (nf & 1)], FC[4 * (nf >> 1) + 2 + (nf & 1)]);
#pragma unroll
        for (int mf = 0; mf < MF; mf++)
            ldsm4(&FA[4 * mf], aLo + (mbase + mf * 16 + r16) * (LDT * 2) + kb);
#pragma unroll
        for (int mf = 0; mf < MF; mf++)
#pragma unroll
            for (int nf = 0; nf < NF; nf++)
                MMA_F16(acc[mf][nf], &FA[4 * mf],
                        FB[4 * (nf >> 1) + (nf & 1)], FB[4 * (nf >> 1) + 2 + (nf & 1)]);
    }
}

// 2-term variant: A hi only, B hi+lo (out projection).
template <int MF, int NF>
__device__ __forceinline__ void mma_chunk2(float (&acc)[MF][NF][4],
                                           uint32_t aHi,
                                           uint32_t bHi, uint32_t bLo,
                                           int mbase, int nbase, int lane)
{
    const int r16 = lane & 15;
    const int koL = (lane >> 4) * 16;
#pragma unroll
    for (int ks = 0; ks < 2; ks++) {
        const int kb = ks * 32 + koL;
        uint32_t FA[4 * MF], FB[2 * NF];
#pragma unroll
        for (int mf = 0; mf < MF; mf++)
            ldsm4(&FA[4 * mf], aHi + (mbase + mf * 16 + r16) * (LDT * 2) + kb);
#pragma unroll
        for (int nb = 0; nb < NF / 2; nb++)
            ldsm4(&FB[4 * nb], bHi + (nbase + nb * 16 + r16) * (LDT * 2) + kb);
#pragma unroll
        for (int mf = 0; mf < MF; mf++)
#pragma unroll
            for (int nf = 0; nf < NF; nf++)
                MMA_F16(acc[mf][nf], &FA[4 * mf],
                        FB[4 * (nf >> 1) + (nf & 1)], FB[4 * (nf >> 1) + 2 + (nf & 1)]);
#pragma unroll
        for (int nb = 0; nb < NF / 2; nb++)
            ldsm4(&FB[4 * nb], bLo + (nbase + nb * 16 + r16) * (LDT * 2) + kb);
#pragma unroll
        for (int mf = 0; mf < MF; mf++)
#pragma unroll
            for (int nf = 0; nf < NF; nf++)
                MMA_F16(acc[mf][nf], &FA[4 * mf],
                        FB[4 * (nf >> 1) + (nf & 1)], FB[4 * (nf >> 1) + 2 + (nf & 1)]);
    }
}

// cp.async a 128x32 fp16 tile (ld = HID) into LDT=40 smem (256 thr)
__device__ __forceinline__ void cp_tile32(const __half* __restrict__ src,
                                          uint32_t dst, int tid) {
#pragma unroll
    for (int i = 0; i < 2; i++) {
        int id = tid + i * 256;
        int r = id >> 2, c = id & 3;
        cp16(dst + r * (LDT * 2) + c * 16, src + (long long)r * HID + c * 8);
    }
}

// ---------------------------------------------------------------------------
// QKV projection (3-term).  grid(8, 64, 3), 256 thr.
// ---------------------------------------------------------------------------
__global__ void __launch_bounds__(256, 2) mm_qkv(
    const float* __restrict__ bq, const float* __restrict__ bk,
    const float* __restrict__ bv)
{
    extern __shared__ char sm[];
    const int z = blockIdx.z;
    const float* bias = (z == 0) ? bq : (z == 1) ? bk : bv;
    __half* dsth = (z == 0) ? g_qh : (z == 1) ? g_kh : g_vh;
    __half* dstl = (z == 0) ? g_ql : (z == 1) ? g_kl : g_vl;

    const int tid = threadIdx.x, lane = tid & 31, wid = tid >> 5;
    const int mw = wid >> 2, nw = wid & 3;
    const int m0 = blockIdx.y * 128, n0 = blockIdx.x * 128;
    const __half* Ah = g_xh + (long long)m0 * HID;
    const __half* Al = g_xl + (long long)m0 * HID;
    const __half* Bh = g_wh + (long long)z * HID * HID + (long long)n0 * HID;
    const __half* Bl = g_wl + (long long)z * HID * HID + (long long)n0 * HID;
    const uint32_t s0 = smem_u32(sm);

    float acc[4][4][4];
#pragma unroll
    for (int i = 0; i < 4; i++)
#pragma unroll
        for (int j = 0; j < 4; j++)
#pragma unroll
            for (int q = 0; q < 4; q++) acc[i][j][q] = 0.f;

    cp_tile32(Ah, s0 + 0 * TILE_B, tid);
    cp_tile32(Al, s0 + 1 * TILE_B, tid);
    cp_tile32(Bh, s0 + 2 * TILE_B, tid);
    cp_tile32(Bl, s0 + 3 * TILE_B, tid);
    CP_COMMIT;

    for (int c = 0; c < 32; c++) {
        if (c + 1 < 32) {
            uint32_t nb = s0 + ((c + 1) & 1) * GBUF;
            cp_tile32(Ah + (c + 1) * 32, nb + 0 * TILE_B, tid);
            cp_tile32(Al + (c + 1) * 32, nb + 1 * TILE_B, tid);
            cp_tile32(Bh + (c + 1) * 32, nb + 2 * TILE_B, tid);
            cp_tile32(Bl + (c + 1) * 32, nb + 3 * TILE_B, tid);
            CP_COMMIT;
            CP_WAIT1;
        } else {
            CP_WAIT0;
        }
        __syncthreads();
        uint32_t buf = s0 + (c & 1) * GBUF;
        mma_chunk3<4, 4>(acc, buf, buf + TILE_B, buf + 2 * TILE_B, buf + 3 * TILE_B,
                         mw * 64, nw * 32, lane);
        __syncthreads();
    }

    const int g = lane >> 2, tig = lane & 3;
#pragma unroll
    for (int mf = 0; mf < 4; mf++) {
#pragma unroll
        for (int half = 0; half < 2; half++) {
            const int m = m0 + mw * 64 + mf * 16 + g + half * 8;
            const int b = m >> 11, s = m & 2047;
#pragma unroll
            for (int nf = 0; nf < 4; nf++) {
                const int n = n0 + nw * 32 + nf * 8 + tig * 2;
                const int h = n >> 6, d = n & 63;
                float vx = acc[mf][nf][half * 2 + 0] + bias[n + 0];
                float vy = acc[mf][nf][half * 2 + 1] + bias[n + 1];
                uint32_t hw, lw;
                pack_hl(vx, vy, hw, lw);
                long long idx = ((long long)(b * NHEAD + h) * SEQ + s) * HDIM + d;
                *(uint32_t*)(dsth + idx) = hw;
                *(uint32_t*)(dstl + idx) = lw;
            }
        }
    }
}

// ---------------------------------------------------------------------------
// Attention, 256 threads, 128-row Q tile, 64-row K/V tiles, 2 CTAs/SM.
// grid(16, 64).
// ---------------------------------------------------------------------------
// 64-row K/V tile with 256 threads (2 cp16 per thread)
__device__ __forceinline__ void cp_kv64(const __half* __restrict__ src,
                                        uint32_t dst, int tid) {
#pragma unroll
    for (int i = 0; i < 2; i++) {
        int id = tid + i * 256;
        int r = id >> 3, c = id & 7;
        cp16(dst + r * LDA_B + c * 16, src + (long long)r * HDIM + c * 8);
    }
}
// 128-row Q tile with 256 threads (4 cp16 per thread)
__device__ __forceinline__ void cp_q128(const __half* __restrict__ src,
                                        uint32_t dst, int tid) {
#pragma unroll
    for (int i = 0; i < 4; i++) {
        int id = tid + i * 256;
        int r = id >> 3, c = id & 7;
        cp16(dst + r * LDA_B + c * 16, src + (long long)r * HDIM + c * 8);
    }
}

// 3-term S tile: Qh*Kh + Qh*Kl + Ql*Kh   (pass B)
__device__ __forceinline__ void s_tile3(float* acc,
                                        const uint32_t* FQh, const uint32_t* FQl,
                                        uint32_t kh, uint32_t kl, int nfp, int lane)
{
    const int r16 = lane & 15;
    const int koL = (lane >> 4) * 16;
    const uint32_t rowoff = (uint32_t)(nfp * 16 + r16) * LDA_B;
#pragma unroll
    for (int ks = 0; ks < 4; ks++) {
        uint32_t FBh[4], FBl[4];
        ldsm4(FBh, kh + rowoff + ks * 32 + koL);
        ldsm4(FBl, kl + rowoff + ks * 32 + koL);
        MMA_F16(acc,     &FQh[4 * ks], FBh[0], FBh[2]);
        MMA_F16(acc + 4, &FQh[4 * ks], FBh[1], FBh[3]);
        MMA_F16(acc,     &FQh[4 * ks], FBl[0], FBl[2]);
        MMA_F16(acc + 4, &FQh[4 * ks], FBl[1], FBl[3]);
        MMA_F16(acc,     &FQl[4 * ks], FBh[0], FBh[2]);
        MMA_F16(acc + 4, &FQl[4 * ks], FBh[1], FBh[3]);
    }
}

// 2-term S tile for pass A sums: Qh*Kh + Ql*Kh
__device__ __forceinline__ void s_tile2(float* acc,
                                        const uint32_t* FQh, const uint32_t* FQl,
                                        uint32_t kh, int nfp, int lane)
{
    const int r16 = lane & 15;
    const int koL = (lane >> 4) * 16;
    const uint32_t rowoff = (uint32_t)(nfp * 16 + r16) * LDA_B;
#pragma unroll
    for (int ks = 0; ks < 4; ks++) {
        uint32_t FBh[4];
        ldsm4(FBh, kh + rowoff + ks * 32 + koL);
        MMA_F16(acc,     &FQh[4 * ks], FBh[0], FBh[2]);
        MMA_F16(acc + 4, &FQh[4 * ks], FBh[1], FBh[3]);
        MMA_F16(acc,     &FQl[4 * ks], FBh[0], FBh[2]);
        MMA_F16(acc + 4, &FQl[4 * ks], FBh[1], FBh[3]);
    }
}

__global__ void __launch_bounds__(256, 2) attn(float* __restrict__ probs)
{
    extern __shared__ char sm[];
    const int tid = threadIdx.x, lane = tid & 31, w = tid >> 5;   // w: 0..7
    const int g = lane >> 2, tig = lane & 3;
    const int bh = blockIdx.y;
    const int m0 = blockIdx.x * 128;
    const uint32_t s0 = smem_u32(sm);

    const __half* Qh = g_qh + ((long long)bh * SEQ + m0) * HDIM;
    const __half* Ql = g_ql + ((long long)bh * SEQ + m0) * HDIM;
    const __half* Kh = g_kh + (long long)bh * SEQ * HDIM;
    const __half* Kl = g_kl + (long long)bh * SEQ * HDIM;
    const __half* Vh = g_vh + (long long)bh * SEQ * HDIM;
    const __half* Vl = g_vl + (long long)bh * SEQ * HDIM;
    float* C = probs + (long long)bh * SEQ * SEQ;

    // Q (group 0), then Kh tiles 0..2 into ring slots 0..2 (groups 1..3)
    cp_q128(Qh, s0 + OQH, tid);
    cp_q128(Ql, s0 + OQL, tid);
    CP_COMMIT;
#pragma unroll
    for (int t = 0; t < 3; t++) {
        cp_kv64(Kh + (long long)t * 64 * HDIM, s0 + OSLOT + t * KT64, tid);
        CP_COMMIT;
    }
    CP_WAIT3;
    __syncthreads();

    uint32_t FQh[16], FQl[16];
    {
        const uint32_t arow = (uint32_t)(w * 16 + (lane & 15)) * LDA_B;
        const uint32_t koL = (lane >> 4) * 16;
#pragma unroll
        for (int ks = 0; ks < 4; ks++) {
            ldsm4(&FQh[4 * ks], s0 + OQH + arow + ks * 32 + koL);
            ldsm4(&FQl[4 * ks], s0 + OQL + arow + ks * 32 + koL);
        }
    }

    // ---------------- pass A: row sums of exp(S2), 4-slot Kh ring ----------
    float sum0 = 0.f, sum1 = 0.f;
    for (int j = 0; j < 32; j++) {
        if (j + 3 < 32)
            cp_kv64(Kh + (long long)(j + 3) * 64 * HDIM,
                    s0 + OSLOT + ((j + 3) & 3) * KT64, tid);
        CP_COMMIT;
        CP_WAIT3;
        __syncthreads();
        const uint32_t kh = s0 + OSLOT + (j & 3) * KT64;
#pragma unroll
        for (int nfp = 0; nfp < 4; nfp++) {
            float acc[8] = {0.f, 0.f, 0.f, 0.f, 0.f, 0.f, 0.f, 0.f};
            s_tile2(acc, FQh, FQl, kh, nfp, lane);
            sum0 += __expf(acc[0]) + __expf(acc[1]) + __expf(acc[4]) + __expf(acc[5]);
            sum1 += __expf(acc[2]) + __expf(acc[3]) + __expf(acc[6]) + __expf(acc[7]);
        }
        __syncthreads();
    }
#pragma unroll
    for (int o = 1; o <= 2; o <<= 1) {
        sum0 += __shfl_xor_sync(0xffffffffu, sum0, o);
        sum1 += __shfl_xor_sync(0xffffffffu, sum1, o);
    }
    const float ri0 = 1.0f / sum0;
    const float ri1 = 1.0f / sum1;

    // ---------------- pass B: write P (3-term S), ctx = Ph (Vh+Vl) --------
    float ctx[8][4];
#pragma unroll
    for (int i = 0; i < 8; i++)
#pragma unroll
        for (int q = 0; q < 4; q++) ctx[i][q] = 0.f;

    {
        uint32_t sl = s0 + OSLOT;
        cp_kv64(Kh, sl, tid);
        cp_kv64(Kl, sl + KT64, tid);
        cp_kv64(Vh, sl + 2 * KT64, tid);
        cp_kv64(Vl, sl + 3 * KT64, tid);
        CP_COMMIT;
    }

    const long long rowg = m0 + w * 16 + g;
    const uint32_t vlanerow = (uint32_t)((lane & 7) + ((lane >> 4) & 1) * 8) * LDA_B
                              + ((lane >> 3) & 1) * 16;

    for (int j = 0; j < 32; j++) {
        if (j + 1 < 32) {
            uint32_t sl = s0 + OSLOT + ((j + 1) & 1) * BSTAGE;
            cp_kv64(Kh + (long long)(j + 1) * 64 * HDIM, sl, tid);
            cp_kv64(Kl + (long long)(j + 1) * 64 * HDIM, sl + KT64, tid);
            cp_kv64(Vh + (long long)(j + 1) * 64 * HDIM, sl + 2 * KT64, tid);
            cp_kv64(Vl + (long long)(j + 1) * 64 * HDIM, sl + 3 * KT64, tid);
        }
        CP_COMMIT;
        CP_WAIT1;
        __syncthreads();
        const uint32_t kh = s0 + OSLOT + (j & 1) * BSTAGE;
        const uint32_t kl = kh + KT64;
        const uint32_t vh = kh + 2 * KT64;
        const uint32_t vl = kh + 3 * KT64;

#pragma unroll
        for (int nfp = 0; nfp < 4; nfp++) {
            float acc[8] = {0.f, 0.f, 0.f, 0.f, 0.f, 0.f, 0.f, 0.f};
            s_tile3(acc, FQh, FQl, kh, kl, nfp, lane);
            float pE0 = __expf(acc[0]) * ri0, pE1 = __expf(acc[1]) * ri0;
            float pE2 = __expf(acc[2]) * ri1, pE3 = __expf(acc[3]) * ri1;
            float pO0 = __expf(acc[4]) * ri0, pO1 = __expf(acc[5]) * ri0;
            float pO2 = __expf(acc[6]) * ri1, pO3 = __expf(acc[7]) * ri1;
            float* Cr = C + rowg * SEQ + j * 64 + nfp * 16 + tig * 2;
            __stcs((float2*)Cr,                 make_float2(pE0, pE1));
            __stcs((float2*)(Cr + 8),           make_float2(pO0, pO1));
            __stcs((float2*)(Cr + 8 * SEQ),     make_float2(pE2, pE3));
            __stcs((float2*)(Cr + 8 * SEQ + 8), make_float2(pO2, pO3));
            uint32_t PAh[4];
            PAh[0] = pack2(pE0, pE1);
            PAh[1] = pack2(pE2, pE3);
            PAh[2] = pack2(pO0, pO1);
            PAh[3] = pack2(pO2, pO3);
            const uint32_t vbase = (uint32_t)(nfp * 16) * LDA_B + vlanerow;
#pragma unroll
            for (int gd = 0; gd < 4; gd++) {
                uint32_t FVh[4], FVl[4];
                ldsm4t(FVh, vh + vbase + gd * 32);
                ldsm4t(FVl, vl + vbase + gd * 32);
                MMA_F16(ctx[2 * gd + 0], PAh, FVh[0], FVh[2]);
                MMA_F16(ctx[2 * gd + 0], PAh, FVl[0], FVl[2]);
                MMA_F16(ctx[2 * gd + 1], PAh, FVh[1], FVh[3]);
                MMA_F16(ctx[2 * gd + 1], PAh, FVl[1], FVl[3]);
            }
        }
        __syncthreads();
    }

    // ctx epilogue -> fp16 (hi only) [b][s][h*64+d]
    const int b = bh >> 4, h = bh & 15;
    const int s = m0 + w * 16 + g;
    const long long base = ((long long)(b * SEQ + s)) * HID + h * HDIM;
#pragma unroll
    for (int dnf = 0; dnf < 8; dnf++) {
        const int d = dnf * 8 + tig * 2;
        *(uint32_t*)(g_ch + base + d) = pack2(ctx[dnf][0], ctx[dnf][1]);
        *(uint32_t*)(g_ch + base + 8LL * HID + d) = pack2(ctx[dnf][2], ctx[dnf][3]);
    }
}

// ---------------------------------------------------------------------------
// Output projection + residual (2-term).  grid(8, 64), 256 thr.
// ---------------------------------------------------------------------------
__global__ void __launch_bounds__(256, 2) mm_out(
    const float* __restrict__ bo, const float* __restrict__ hidden,
    float* __restrict__ out)
{
    extern __shared__ char sm[];
    const int tid = threadIdx.x, lane = tid & 31, wid = tid >> 5;
    const int mw = wid >> 2, nw = wid & 3;
    const int m0 = blockIdx.y * 128, n0 = blockIdx.x * 128;
    const __half* Ah = g_ch + (long long)m0 * HID;
    const __half* Bh = g_wh + 3LL * HID * HID + (long long)n0 * HID;
    const __half* Bl = g_wl + 3LL * HID * HID + (long long)n0 * HID;
    const uint32_t s0 = smem_u32(sm);

    float acc[4][4][4];
#pragma unroll
    for (int i = 0; i < 4; i++)
#pragma unroll
        for (int j = 0; j < 4; j++)
#pragma unroll
            for (int q = 0; q < 4; q++) acc[i][j][q] = 0.f;

    cp_tile32(Ah, s0 + 0 * TILE_B, tid);
    cp_tile32(Bh, s0 + 1 * TILE_B, tid);
    cp_tile32(Bl, s0 + 2 * TILE_B, tid);
    CP_COMMIT;

    for (int c = 0; c < 32; c++) {
        if (c + 1 < 32) {
            uint32_t nb = s0 + ((c + 1) & 1) * GBUF2;
            cp_tile32(Ah + (c + 1) * 32, nb + 0 * TILE_B, tid);
            cp_tile32(Bh + (c + 1) * 32, nb + 1 * TILE_B, tid);
            cp_tile32(Bl + (c + 1) * 32, nb + 2 * TILE_B, tid);
            CP_COMMIT;
            CP_WAIT1;
        } else {
            CP_WAIT0;
        }
        __syncthreads();
        uint32_t buf = s0 + (c & 1) * GBUF2;
        mma_chunk2<4, 4>(acc, buf, buf + TILE_B, buf + 2 * TILE_B,
                         mw * 64, nw * 32, lane);
        __syncthreads();
    }

    const int g = lane >> 2, tig = lane & 3;
#pragma unroll
    for (int mf = 0; mf < 4; mf++) {
#pragma unroll
        for (int half = 0; half < 2; half++) {
            const long long m = m0 + mw * 64 + mf * 16 + g + half * 8;
#pragma unroll
            for (int nf = 0; nf < 4; nf++) {
                const int n = n0 + nw * 32 + nf * 8 + tig * 2;
                float2 hd = *(const float2*)(hidden + m * HID + n);
                float2 st;
                st.x = acc[mf][nf][half * 2 + 0] + bo[n + 0] + hd.x;
                st.y = acc[mf][nf][half * 2 + 1] + bo[n + 1] + hd.y;
                *(float2*)(out + m * HID + n) = st;
            }
        }
    }
}

// ---------------------------------------------------------------------------
extern "C" void kernel_launch(void* const* d_in, const int* in_sizes, int n_in,
                              void* d_out, int out_size)
{
    const float* X  = (const float*)d_in[0];
    const float* Wq = (const float*)d_in[1];
    const float* bq = (const float*)d_in[2];
    const float* Wk = (const float*)d_in[3];
    const float* bk = (const float*)d_in[4];
    const float* Wv = (const float*)d_in[5];
    const float* bv = (const float*)d_in[6];
    const float* Wo = (const float*)d_in[7];
    const float* bo = (const float*)d_in[8];

    float* out   = (float*)d_out;
    float* probs = out + OUT_ELEMS;

    cudaFuncSetAttribute(mm_qkv, cudaFuncAttributeMaxDynamicSharedMemorySize, SMEM_G);
    cudaFuncSetAttribute(mm_out, cudaFuncAttributeMaxDynamicSharedMemorySize, SMEM_G2);
    cudaFuncSetAttribute(attn,   cudaFuncAttributeMaxDynamicSharedMemorySize, SMEM_ATTN);

    const long long NPREP = (long long)MROWS * HID + 4LL * HID * HID;
    prep<<<(unsigned)((NPREP + 255) / 256), 256>>>(X, Wq, Wk, Wv, Wo);
    mm_qkv<<<dim3(HID / 128, MROWS / 128, 3), 256, SMEM_G>>>(bq, bk, bv);
    attn<<<dim3(SEQ / 128, BATCH * NHEAD), 256, SMEM_ATTN>>>(probs);
    mm_out<<<dim3(HID / 128, MROWS / 128), 256, SMEM_G2>>>(bo, X, out);
}

// round 14
// speedup vs baseline: 1.2792x; 1.0347x over previous
#include <cuda_runtime.h>
#include <cuda_fp16.h>
#include <cstdint>

// ---------------------------------------------------------------------------
constexpr int BATCH = 4;
constexpr int SEQ   = 2048;
constexpr int HID   = 1024;
constexpr int NHEAD = 16;
constexpr int HDIM  = 64;
constexpr int MROWS = BATCH * SEQ;                       // 8192
constexpr long long OUT_ELEMS = (long long)MROWS * HID;  // 8,388,608

// GEMM tiles: 32-col chunks, rows padded to 40 fp16 (80 B = 16B-aligned rows)
constexpr int LDT = 40;
constexpr int TILE_B = 128 * LDT * 2;     // 10240
constexpr int GBUF   = 4 * TILE_B;        // qkv: Ah,Al,Bh,Bl = 40960
constexpr int SMEM_G = 2 * GBUF;          // 81920 (2-stage, 2 CTAs/SM)
constexpr int GBUF2  = 3 * TILE_B;        // out: Ah,Bh,Bl = 30720
constexpr int SMEM_G2 = 3 * GBUF2;        // 92160 (3-stage single-sync, 2 CTAs/SM)

// Attention tiles: 64-col rows padded to 72 fp16 (144 B = 16B-aligned rows)
constexpr int LDA_B  = 144;
constexpr int QTILE  = 128 * LDA_B;       // 18432
constexpr int KT64   = 64 * LDA_B;        // 9216
constexpr int OQH = 0;
constexpr int OQL = QTILE;                // Q region: 0..36864, dead after prologue
constexpr int OSA = 2 * QTILE;            // 36864: pass A ring, 3 slots x 9216
constexpr int BGRP = 4 * KT64;            // 36864: pass B group (Kh,Kl,Vh,Vl)
constexpr int SMEM_ATTN = 3 * BGRP;       // 110592 (pass B ring reuses Q region)

// ---------------------------------------------------------------------------
// Prepped fp16 hi/lo operands
// ---------------------------------------------------------------------------
__device__ __half g_xh[MROWS * HID], g_xl[MROWS * HID];
__device__ __half g_wh[4 * HID * HID], g_wl[4 * HID * HID];
__device__ __half g_qh[64 * SEQ * HDIM], g_ql[64 * SEQ * HDIM];
__device__ __half g_kh[64 * SEQ * HDIM], g_kl[64 * SEQ * HDIM];
__device__ __half g_vh[64 * SEQ * HDIM], g_vl[64 * SEQ * HDIM];
__device__ __half g_ch[MROWS * HID];     // ctx: hi only

// ---------------------------------------------------------------------------
__device__ __forceinline__ uint32_t smem_u32(const void* p) {
    uint32_t a;
    asm("{ .reg .u64 t; cvta.to.shared.u64 t, %1; cvt.u32.u64 %0, t; }"
        : "=r"(a) : "l"(p));
    return a;
}

__device__ __forceinline__ void ldsm4(uint32_t* r, uint32_t a) {
    asm volatile("ldmatrix.sync.aligned.m8n8.x4.shared.b16 {%0,%1,%2,%3}, [%4];"
                 : "=r"(r[0]), "=r"(r[1]), "=r"(r[2]), "=r"(r[3]) : "r"(a));
}
__device__ __forceinline__ void ldsm4t(uint32_t* r, uint32_t a) {
    asm volatile("ldmatrix.sync.aligned.m8n8.x4.trans.shared.b16 {%0,%1,%2,%3}, [%4];"
                 : "=r"(r[0]), "=r"(r[1]), "=r"(r[2]), "=r"(r[3]) : "r"(a));
}

#define MMA_F16(d, a, b0, b1)                                               \
    asm volatile(                                                           \
        "mma.sync.aligned.m16n8k16.row.col.f32.f16.f16.f32 "                \
        "{%0,%1,%2,%3}, {%4,%5,%6,%7}, {%8,%9}, {%0,%1,%2,%3};"             \
        : "+f"((d)[0]), "+f"((d)[1]), "+f"((d)[2]), "+f"((d)[3])            \
        : "r"((a)[0]), "r"((a)[1]), "r"((a)[2]), "r"((a)[3]),               \
          "r"(b0), "r"(b1))

__device__ __forceinline__ void cp16(uint32_t dst, const void* src) {
    asm volatile("cp.async.cg.shared.global [%0], [%1], 16;" :: "r"(dst), "l"(src));
}
#define CP_COMMIT asm volatile("cp.async.commit_group;" ::: "memory")
#define CP_WAIT1  asm volatile("cp.async.wait_group 1;" ::: "memory")
#define CP_WAIT0  asm volatile("cp.async.wait_group 0;" ::: "memory")

__device__ __forceinline__ uint32_t pack2(float x, float y) {
    __half2 h = __floats2half2_rn(x, y);
    return *(uint32_t*)&h;
}

__device__ __forceinline__ void pack_hl(float x, float y, uint32_t& h, uint32_t& l) {
    __half hx = __float2half_rn(x);
    __half hy = __float2half_rn(y);
    __half lx = __float2half_rn(x - __half2float(hx));
    __half ly = __float2half_rn(y - __half2float(hy));
    h = ((uint32_t)__half_as_ushort(hy) << 16) | __half_as_ushort(hx);
    l = ((uint32_t)__half_as_ushort(ly) << 16) | __half_as_ushort(lx);
}

// ---------------------------------------------------------------------------
// prep: split X and the 4 weight matrices into fp16 hi/lo once.
// ---------------------------------------------------------------------------
__global__ void __launch_bounds__(256) prep(
    const float* __restrict__ X,  const float* __restrict__ Wq,
    const float* __restrict__ Wk, const float* __restrict__ Wv,
    const float* __restrict__ Wo)
{
    const long long NX = (long long)MROWS * HID;
    long long i = (long long)blockIdx.x * 256 + threadIdx.x;
    float v; __half *dh, *dl; long long o;
    if (i < NX) {
        v = X[i]; dh = g_xh; dl = g_xl; o = i;
    } else {
        long long j = i - NX;
        int w = (int)(j >> 20);
        long long r = j & 1048575;
        if (w == 0) v = Wq[r]; else if (w == 1) v = Wk[r];
        else if (w == 2) v = Wv[r]; else v = Wo[r];
        dh = g_wh; dl = g_wl; o = j;
    }
    __half hb = __float2half_rn(v);
    dh[o] = hb;
    dl[o] = __float2half_rn(v - __half2float(hb));
}

// ---------------------------------------------------------------------------
// 3-term split-fp16 warp MMA over one 32-wide K chunk (qkv).
// ---------------------------------------------------------------------------
template <int MF, int NF>
__device__ __forceinline__ void mma_chunk3(float (&acc)[MF][NF][4],
                                           uint32_t aHi, uint32_t aLo,
                                           uint32_t bHi, uint32_t bLo,
                                           int mbase, int nbase, int lane)
{
    const int r16 = lane & 15;
    const int koL = (lane >> 4) * 16;
#pragma unroll
    for (int ks = 0; ks < 2; ks++) {
        const int kb = ks * 32 + koL;
        uint32_t FA[4 * MF], FB[2 * NF], FC[2 * NF];
#pragma unroll
        for (int mf = 0; mf < MF; mf++)
            ldsm4(&FA[4 * mf], aHi + (mbase + mf * 16 + r16) * (LDT * 2) + kb);
#pragma unroll
        for (int nb = 0; nb < NF / 2; nb++)
            ldsm4(&FB[4 * nb], bHi + (nbase + nb * 16 + r16) * (LDT * 2) + kb);
#pragma unroll
        for (int mf = 0; mf < MF; mf++)
#pragma unroll
            for (int nf = 0; nf < NF; nf++)
                MMA_F16(acc[mf][nf], &FA[4 * mf],
                        FB[4 * (nf >> 1) + (nf & 1)], FB[4 * (nf >> 1) + 2 + (nf & 1)]);
#pragma unroll
        for (int nb = 0; nb < NF / 2; nb++)
            ldsm4(&FC[4 * nb], bLo + (nbase + nb * 16 + r16) * (LDT * 2) + kb);
#pragma unroll
        for (int mf = 0; mf < MF; mf++)
#pragma unroll
            for (int nf = 0; nf < NF; nf++)
                MMA_F16(acc[mf][nf], &FA[4 * mf],
                        FC[4 * (nf >> 1) + (nf & 1)], FC[4 * (nf >> 1) + 2 + (nf & 1)]);
#pragma unroll
        for (int mf = 0; mf < MF; mf++)
            ldsm4(&FA[4 * mf], aLo + (mbase + mf * 16 + r16) * (LDT * 2) + kb);
#pragma unroll
        for (int mf = 0; mf < MF; mf++)
#pragma unroll
            for (int nf = 0; nf < NF; nf++)
                MMA_F16(acc[mf][nf], &FA[4 * mf],
                        FB[4 * (nf >> 1) + (nf & 1)], FB[4 * (nf >> 1) + 2 + (nf & 1)]);
    }
}

// 2-term variant: A hi only, B hi+lo (out projection).
template <int MF, int NF>
__device__ __forceinline__ void mma_chunk2(float (&acc)[MF][NF][4],
                                           uint32_t aHi,
                                           uint32_t bHi, uint32_t bLo,
                                           int mbase, int nbase, int lane)
{
    const int r16 = lane & 15;
    const int koL = (lane >> 4) * 16;
#pragma unroll
    for (int ks = 0; ks < 2; ks++) {
        const int kb = ks * 32 + koL;
        uint32_t FA[4 * MF], FB[2 * NF];
#pragma unroll
        for (int mf = 0; mf < MF; mf++)
            ldsm4(&FA[4 * mf], aHi + (mbase + mf * 16 + r16) * (LDT * 2) + kb);
#pragma unroll
        for (int nb = 0; nb < NF / 2; nb++)
            ldsm4(&FB[4 * nb], bHi + (nbase + nb * 16 + r16) * (LDT * 2) + kb);
#pragma unroll
        for (int mf = 0; mf < MF; mf++)
#pragma unroll
            for (int nf = 0; nf < NF; nf++)
                MMA_F16(acc[mf][nf], &FA[4 * mf],
                        FB[4 * (nf >> 1) + (nf & 1)], FB[4 * (nf >> 1) + 2 + (nf & 1)]);
#pragma unroll
        for (int nb = 0; nb < NF / 2; nb++)
            ldsm4(&FB[4 * nb], bLo + (nbase + nb * 16 + r16) * (LDT * 2) + kb);
#pragma unroll
        for (int mf = 0; mf < MF; mf++)
#pragma unroll
            for (int nf = 0; nf < NF; nf++)
                MMA_F16(acc[mf][nf], &FA[4 * mf],
                        FB[4 * (nf >> 1) + (nf & 1)], FB[4 * (nf >> 1) + 2 + (nf & 1)]);
    }
}

// cp.async a 128x32 fp16 tile (ld = HID) into LDT=40 smem (256 thr)
__device__ __forceinline__ void cp_tile32(const __half* __restrict__ src,
                                          uint32_t dst, int tid) {
#pragma unroll
    for (int i = 0; i < 2; i++) {
        int id = tid + i * 256;
        int r = id >> 2, c = id & 3;
        cp16(dst + r * (LDT * 2) + c * 16, src + (long long)r * HID + c * 8);
    }
}

// ---------------------------------------------------------------------------
// QKV projection (3-term, 2-stage double buffer — proven R9 form).
// grid(8, 64, 3), 256 thr.
// ---------------------------------------------------------------------------
__global__ void __launch_bounds__(256, 2) mm_qkv(
    const float* __restrict__ bq, const float* __restrict__ bk,
    const float* __restrict__ bv)
{
    extern __shared__ char sm[];
    const int z = blockIdx.z;
    const float* bias = (z == 0) ? bq : (z == 1) ? bk : bv;
    __half* dsth = (z == 0) ? g_qh : (z == 1) ? g_kh : g_vh;
    __half* dstl = (z == 0) ? g_ql : (z == 1) ? g_kl : g_vl;

    const int tid = threadIdx.x, lane = tid & 31, wid = tid >> 5;
    const int mw = wid >> 2, nw = wid & 3;
    const int m0 = blockIdx.y * 128, n0 = blockIdx.x * 128;
    const __half* Ah = g_xh + (long long)m0 * HID;
    const __half* Al = g_xl + (long long)m0 * HID;
    const __half* Bh = g_wh + (long long)z * HID * HID + (long long)n0 * HID;
    const __half* Bl = g_wl + (long long)z * HID * HID + (long long)n0 * HID;
    const uint32_t s0 = smem_u32(sm);

    float acc[4][4][4];
#pragma unroll
    for (int i = 0; i < 4; i++)
#pragma unroll
        for (int j = 0; j < 4; j++)
#pragma unroll
            for (int q = 0; q < 4; q++) acc[i][j][q] = 0.f;

    cp_tile32(Ah, s0 + 0 * TILE_B, tid);
    cp_tile32(Al, s0 + 1 * TILE_B, tid);
    cp_tile32(Bh, s0 + 2 * TILE_B, tid);
    cp_tile32(Bl, s0 + 3 * TILE_B, tid);
    CP_COMMIT;

    for (int c = 0; c < 32; c++) {
        if (c + 1 < 32) {
            uint32_t nb = s0 + ((c + 1) & 1) * GBUF;
            cp_tile32(Ah + (c + 1) * 32, nb + 0 * TILE_B, tid);
            cp_tile32(Al + (c + 1) * 32, nb + 1 * TILE_B, tid);
            cp_tile32(Bh + (c + 1) * 32, nb + 2 * TILE_B, tid);
            cp_tile32(Bl + (c + 1) * 32, nb + 3 * TILE_B, tid);
            CP_COMMIT;
            CP_WAIT1;
        } else {
            CP_WAIT0;
        }
        __syncthreads();
        uint32_t buf = s0 + (c & 1) * GBUF;
        mma_chunk3<4, 4>(acc, buf, buf + TILE_B, buf + 2 * TILE_B, buf + 3 * TILE_B,
                         mw * 64, nw * 32, lane);
        __syncthreads();
    }

    const int g = lane >> 2, tig = lane & 3;
#pragma unroll
    for (int mf = 0; mf < 4; mf++) {
#pragma unroll
        for (int half = 0; half < 2; half++) {
            const int m = m0 + mw * 64 + mf * 16 + g + half * 8;
            const int b = m >> 11, s = m & 2047;
#pragma unroll
            for (int nf = 0; nf < 4; nf++) {
                const int n = n0 + nw * 32 + nf * 8 + tig * 2;
                const int h = n >> 6, d = n & 63;
                float vx = acc[mf][nf][half * 2 + 0] + bias[n + 0];
                float vy = acc[mf][nf][half * 2 + 1] + bias[n + 1];
                uint32_t hw, lw;
                pack_hl(vx, vy, hw, lw);
                long long idx = ((long long)(b * NHEAD + h) * SEQ + s) * HDIM + d;
                *(uint32_t*)(dsth + idx) = hw;
                *(uint32_t*)(dstl + idx) = lw;
            }
        }
    }
}

// ---------------------------------------------------------------------------
// Attention, 256 threads, 128-row Q, 64-row K/V, 2 CTAs/SM, single-sync rings.
// grid(16, 64).
// ---------------------------------------------------------------------------
__device__ __forceinline__ void cp_kv64(const __half* __restrict__ src,
                                        uint32_t dst, int tid) {
#pragma unroll
    for (int i = 0; i < 2; i++) {
        int id = tid + i * 256;
        int r = id >> 3, c = id & 7;
        cp16(dst + r * LDA_B + c * 16, src + (long long)r * HDIM + c * 8);
    }
}
__device__ __forceinline__ void cp_q128(const __half* __restrict__ src,
                                        uint32_t dst, int tid) {
#pragma unroll
    for (int i = 0; i < 4; i++) {
        int id = tid + i * 256;
        int r = id >> 3, c = id & 7;
        cp16(dst + r * LDA_B + c * 16, src + (long long)r * HDIM + c * 8);
    }
}

// 3-term S tile: Qh*Kh + Qh*Kl + Ql*Kh   (pass B)
__device__ __forceinline__ void s_tile3(float* acc,
                                        const uint32_t* FQh, const uint32_t* FQl,
                                        uint32_t kh, uint32_t kl, int nfp, int lane)
{
    const int r16 = lane & 15;
    const int koL = (lane >> 4) * 16;
    const uint32_t rowoff = (uint32_t)(nfp * 16 + r16) * LDA_B;
#pragma unroll
    for (int ks = 0; ks < 4; ks++) {
        uint32_t FBh[4], FBl[4];
        ldsm4(FBh, kh + rowoff + ks * 32 + koL);
        ldsm4(FBl, kl + rowoff + ks * 32 + koL);
        MMA_F16(acc,     &FQh[4 * ks], FBh[0], FBh[2]);
        MMA_F16(acc + 4, &FQh[4 * ks], FBh[1], FBh[3]);
        MMA_F16(acc,     &FQh[4 * ks], FBl[0], FBl[2]);
        MMA_F16(acc + 4, &FQh[4 * ks], FBl[1], FBl[3]);
        MMA_F16(acc,     &FQl[4 * ks], FBh[0], FBh[2]);
        MMA_F16(acc + 4, &FQl[4 * ks], FBh[1], FBh[3]);
    }
}

// 2-term S tile for pass A sums: Qh*Kh + Ql*Kh
__device__ __forceinline__ void s_tile2(float* acc,
                                        const uint32_t* FQh, const uint32_t* FQl,
                                        uint32_t kh, int nfp, int lane)
{
    const int r16 = lane & 15;
    const int koL = (lane >> 4) * 16;
    const uint32_t rowoff = (uint32_t)(nfp * 16 + r16) * LDA_B;
#pragma unroll
    for (int ks = 0; ks < 4; ks++) {
        uint32_t FBh[4];
        ldsm4(FBh, kh + rowoff + ks * 32 + koL);
        MMA_F16(acc,     &FQh[4 * ks], FBh[0], FBh[2]);
        MMA_F16(acc + 4, &FQh[4 * ks], FBh[1], FBh[3]);
        MMA_F16(acc,     &FQl[4 * ks], FBh[0], FBh[2]);
        MMA_F16(acc + 4, &FQl[4 * ks], FBh[1], FBh[3]);
    }
}

__global__ void __launch_bounds__(256, 2) attn(float* __restrict__ probs)
{
    extern __shared__ char sm[];
    const int tid = threadIdx.x, lane = tid & 31, w = tid >> 5;   // w: 0..7
    const int g = lane >> 2, tig = lane & 3;
    const int bh = blockIdx.y;
    const int m0 = blockIdx.x * 128;
    const uint32_t s0 = smem_u32(sm);

    const __half* Qh = g_qh + ((long long)bh * SEQ + m0) * HDIM;
    const __half* Ql = g_ql + ((long long)bh * SEQ + m0) * HDIM;
    const __half* Kh = g_kh + (long long)bh * SEQ * HDIM;
    const __half* Kl = g_kl + (long long)bh * SEQ * HDIM;
    const __half* Vh = g_vh + (long long)bh * SEQ * HDIM;
    const __half* Vl = g_vl + (long long)bh * SEQ * HDIM;
    float* C = probs + (long long)bh * SEQ * SEQ;

    // prologue: Q (group), K0 into pass-A slot 0 (group)
    cp_q128(Qh, s0 + OQH, tid);
    cp_q128(Ql, s0 + OQL, tid);
    CP_COMMIT;
    cp_kv64(Kh, s0 + OSA, tid);
    CP_COMMIT;
    CP_WAIT1;           // Q done (K0 may be in flight)
    __syncthreads();

    uint32_t FQh[16], FQl[16];
    {
        const uint32_t arow = (uint32_t)(w * 16 + (lane & 15)) * LDA_B;
        const uint32_t koL = (lane >> 4) * 16;
#pragma unroll
        for (int ks = 0; ks < 4; ks++) {
            ldsm4(&FQh[4 * ks], s0 + OQH + arow + ks * 32 + koL);
            ldsm4(&FQl[4 * ks], s0 + OQL + arow + ks * 32 + koL);
        }
    }
    // Q smem region is dead from here on (fragments live in registers)

    // ---------------- pass A: 3-slot Kh ring, single sync/iter ------------
    float sum0 = 0.f, sum1 = 0.f;
    for (int j = 0; j < 32; j++) {
        if (j + 1 < 32)
            cp_kv64(Kh + (long long)(j + 1) * 64 * HDIM,
                    s0 + OSA + ((j + 1) % 3) * KT64, tid);
        CP_COMMIT;
        CP_WAIT1;
        __syncthreads();
        const uint32_t kh = s0 + OSA + (j % 3) * KT64;
#pragma unroll
        for (int nfp = 0; nfp < 4; nfp++) {
            float acc[8] = {0.f, 0.f, 0.f, 0.f, 0.f, 0.f, 0.f, 0.f};
            s_tile2(acc, FQh, FQl, kh, nfp, lane);
            sum0 += __expf(acc[0]) + __expf(acc[1]) + __expf(acc[4]) + __expf(acc[5]);
            sum1 += __expf(acc[2]) + __expf(acc[3]) + __expf(acc[6]) + __expf(acc[7]);
        }
    }
#pragma unroll
    for (int o = 1; o <= 2; o <<= 1) {
        sum0 += __shfl_xor_sync(0xffffffffu, sum0, o);
        sum1 += __shfl_xor_sync(0xffffffffu, sum1, o);
    }
    const float ri0 = 1.0f / sum0;
    const float ri1 = 1.0f / sum1;

    // ---------------- pass B: 3-group KV ring (reuses Q region) -----------
    float ctx[8][4];
#pragma unroll
    for (int i = 0; i < 8; i++)
#pragma unroll
        for (int q = 0; q < 4; q++) ctx[i][q] = 0.f;

    // group 0 lives at offset 0 (= dead Q region): safe to fill while
    // stragglers finish pass A (they only touch OSA and registers).
    {
        uint32_t sl = s0;
        cp_kv64(Kh, sl, tid);
        cp_kv64(Kl, sl + KT64, tid);
        cp_kv64(Vh, sl + 2 * KT64, tid);
        cp_kv64(Vl, sl + 3 * KT64, tid);
        CP_COMMIT;
    }
    __syncthreads();   // all warps past pass A before group 1 overwrites OSA

    const long long rowg = m0 + w * 16 + g;
    const uint32_t vlanerow = (uint32_t)((lane & 7) + ((lane >> 4) & 1) * 8) * LDA_B
                              + ((lane >> 3) & 1) * 16;

    for (int j = 0; j < 32; j++) {
        if (j + 1 < 32) {
            uint32_t sl = s0 + ((j + 1) % 3) * BGRP;
            cp_kv64(Kh + (long long)(j + 1) * 64 * HDIM, sl, tid);
            cp_kv64(Kl + (long long)(j + 1) * 64 * HDIM, sl + KT64, tid);
            cp_kv64(Vh + (long long)(j + 1) * 64 * HDIM, sl + 2 * KT64, tid);
            cp_kv64(Vl + (long long)(j + 1) * 64 * HDIM, sl + 3 * KT64, tid);
        }
        CP_COMMIT;
        CP_WAIT1;
        __syncthreads();
        const uint32_t kh = s0 + (j % 3) * BGRP;
        const uint32_t kl = kh + KT64;
        const uint32_t vh = kh + 2 * KT64;
        const uint32_t vl = kh + 3 * KT64;

#pragma unroll
        for (int nfp = 0; nfp < 4; nfp++) {
            float acc[8] = {0.f, 0.f, 0.f, 0.f, 0.f, 0.f, 0.f, 0.f};
            s_tile3(acc, FQh, FQl, kh, kl, nfp, lane);
            float pE0 = __expf(acc[0]) * ri0, pE1 = __expf(acc[1]) * ri0;
            float pE2 = __expf(acc[2]) * ri1, pE3 = __expf(acc[3]) * ri1;
            float pO0 = __expf(acc[4]) * ri0, pO1 = __expf(acc[5]) * ri0;
            float pO2 = __expf(acc[6]) * ri1, pO3 = __expf(acc[7]) * ri1;
            float* Cr = C + rowg * SEQ + j * 64 + nfp * 16 + tig * 2;
            __stcs((float2*)Cr,                 make_float2(pE0, pE1));
            __stcs((float2*)(Cr + 8),           make_float2(pO0, pO1));
            __stcs((float2*)(Cr + 8 * SEQ),     make_float2(pE2, pE3));
            __stcs((float2*)(Cr + 8 * SEQ + 8), make_float2(pO2, pO3));
            uint32_t PAh[4];
            PAh[0] = pack2(pE0, pE1);
            PAh[1] = pack2(pE2, pE3);
            PAh[2] = pack2(pO0, pO1);
            PAh[3] = pack2(pO2, pO3);
            const uint32_t vbase = (uint32_t)(nfp * 16) * LDA_B + vlanerow;
#pragma unroll
            for (int gd = 0; gd < 4; gd++) {
                uint32_t FVh[4], FVl[4];
                ldsm4t(FVh, vh + vbase + gd * 32);
                ldsm4t(FVl, vl + vbase + gd * 32);
                MMA_F16(ctx[2 * gd + 0], PAh, FVh[0], FVh[2]);
                MMA_F16(ctx[2 * gd + 0], PAh, FVl[0], FVl[2]);
                MMA_F16(ctx[2 * gd + 1], PAh, FVh[1], FVh[3]);
                MMA_F16(ctx[2 * gd + 1], PAh, FVl[1], FVl[3]);
            }
        }
    }

    // ctx epilogue -> fp16 (hi only) [b][s][h*64+d]
    const int b = bh >> 4, h = bh & 15;
    const int s = m0 + w * 16 + g;
    const long long base = ((long long)(b * SEQ + s)) * HID + h * HDIM;
#pragma unroll
    for (int dnf = 0; dnf < 8; dnf++) {
        const int d = dnf * 8 + tig * 2;
        *(uint32_t*)(g_ch + base + d) = pack2(ctx[dnf][0], ctx[dnf][1]);
        *(uint32_t*)(g_ch + base + 8LL * HID + d) = pack2(ctx[dnf][2], ctx[dnf][3]);
    }
}

// ---------------------------------------------------------------------------
// Output projection + residual (2-term, 3-stage single-sync).  grid(8, 64).
// ---------------------------------------------------------------------------
__global__ void __launch_bounds__(256, 2) mm_out(
    const float* __restrict__ bo, const float* __restrict__ hidden,
    float* __restrict__ out)
{
    extern __shared__ char sm[];
    const int tid = threadIdx.x, lane = tid & 31, wid = tid >> 5;
    const int mw = wid >> 2, nw = wid & 3;
    const int m0 = blockIdx.y * 128, n0 = blockIdx.x * 128;
    const __half* Ah = g_ch + (long long)m0 * HID;
    const __half* Bh = g_wh + 3LL * HID * HID + (long long)n0 * HID;
    const __half* Bl = g_wl + 3LL * HID * HID + (long long)n0 * HID;
    const uint32_t s0 = smem_u32(sm);

    float acc[4][4][4];
#pragma unroll
    for (int i = 0; i < 4; i++)
#pragma unroll
        for (int j = 0; j < 4; j++)
#pragma unroll
            for (int q = 0; q < 4; q++) acc[i][j][q] = 0.f;

    cp_tile32(Ah, s0 + 0 * TILE_B, tid);
    cp_tile32(Bh, s0 + 1 * TILE_B, tid);
    cp_tile32(Bl, s0 + 2 * TILE_B, tid);
    CP_COMMIT;

    for (int c = 0; c < 32; c++) {
        if (c + 1 < 32) {
            uint32_t nb = s0 + ((c + 1) % 3) * GBUF2;
            cp_tile32(Ah + (c + 1) * 32, nb + 0 * TILE_B, tid);
            cp_tile32(Bh + (c + 1) * 32, nb + 1 * TILE_B, tid);
            cp_tile32(Bl + (c + 1) * 32, nb + 2 * TILE_B, tid);
        }
        CP_COMMIT;
        CP_WAIT1;
        __syncthreads();
        uint32_t buf = s0 + (c % 3) * GBUF2;
        mma_chunk2<4, 4>(acc, buf, buf + TILE_B, buf + 2 * TILE_B,
                         mw * 64, nw * 32, lane);
        // single-sync: 3-stage ring, distance-1 prefetch is race-free
    }

    const int g = lane >> 2, tig = lane & 3;
#pragma unroll
    for (int mf = 0; mf < 4; mf++) {
#pragma unroll
        for (int half = 0; half < 2; half++) {
            const long long m = m0 + mw * 64 + mf * 16 + g + half * 8;
#pragma unroll
            for (int nf = 0; nf < 4; nf++) {
                const int n = n0 + nw * 32 + nf * 8 + tig * 2;
                float2 hd = *(const float2*)(hidden + m * HID + n);
                float2 st;
                st.x = acc[mf][nf][half * 2 + 0] + bo[n + 0] + hd.x;
                st.y = acc[mf][nf][half * 2 + 1] + bo[n + 1] + hd.y;
                *(float2*)(out + m * HID + n) = st;
            }
        }
    }
}

// ---------------------------------------------------------------------------
extern "C" void kernel_launch(void* const* d_in, const int* in_sizes, int n_in,
                              void* d_out, int out_size)
{
    const float* X  = (const float*)d_in[0];
    const float* Wq = (const float*)d_in[1];
    const float* bq = (const float*)d_in[2];
    const float* Wk = (const float*)d_in[3];
    const float* bk = (const float*)d_in[4];
    const float* Wv = (const float*)d_in[5];
    const float* bv = (const float*)d_in[6];
    const float* Wo = (const float*)d_in[7];
    const float* bo = (const float*)d_in[8];

    float* out   = (float*)d_out;
    float* probs = out + OUT_ELEMS;

    cudaFuncSetAttribute(mm_qkv, cudaFuncAttributeMaxDynamicSharedMemorySize, SMEM_G);
    cudaFuncSetAttribute(mm_out, cudaFuncAttributeMaxDynamicSharedMemorySize, SMEM_G2);
    cudaFuncSetAttribute(attn,   cudaFuncAttributeMaxDynamicSharedMemorySize, SMEM_ATTN);

    const long long NPREP = (long long)MROWS * HID + 4LL * HID * HID;
    prep<<<(unsigned)((NPREP + 255) / 256), 256>>>(X, Wq, Wk, Wv, Wo);
    mm_qkv<<<dim3(HID / 128, MROWS / 128, 3), 256, SMEM_G>>>(bq, bk, bv);
    attn<<<dim3(SEQ / 128, BATCH * NHEAD), 256, SMEM_ATTN>>>(probs);
    mm_out<<<dim3(HID / 128, MROWS / 128), 256, SMEM_G2>>>(bo, X, out);
}

// round 15
// speedup vs baseline: 1.2904x; 1.0087x over previous
#include <cuda_runtime.h>
#include <cuda_fp16.h>
#include <cstdint>

// ---------------------------------------------------------------------------
constexpr int BATCH = 4;
constexpr int SEQ   = 2048;
constexpr int HID   = 1024;
constexpr int NHEAD = 16;
constexpr int HDIM  = 64;
constexpr int MROWS = BATCH * SEQ;                       // 8192
constexpr long long OUT_ELEMS = (long long)MROWS * HID;  // 8,388,608

// GEMM tiles: 32-col chunks, rows padded to 40 fp16 (80 B = 16B-aligned rows)
constexpr int LDT = 40;
constexpr int TILE_B = 128 * LDT * 2;     // 10240
constexpr int GBUF   = 4 * TILE_B;        // qkv: Ah,Al,Bh,Bl = 40960
constexpr int SMEM_G = 2 * GBUF;          // 81920 (2-stage, 2 CTAs/SM)
constexpr int GBUF2  = 3 * TILE_B;        // out: Ah,Bh,Bl = 30720
constexpr int SMEM_G2 = 3 * GBUF2;        // 92160 (3-stage single-sync)

// Attention tiles: 64-col rows padded to 72 fp16 (144 B = 16B-aligned rows)
constexpr int LDA_B  = 144;
constexpr int QTILE  = 128 * LDA_B;       // 18432
constexpr int KT64   = 64 * LDA_B;        // 9216
constexpr int KT128  = 128 * LDA_B;       // 18432 (pass-A K tile)
constexpr int OQH = 0;
constexpr int OQL = QTILE;                // Q region: 0..36864, dead after prologue
constexpr int OSA = 2 * QTILE;            // 36864: pass A ring, 3 slots x KT128
constexpr int BGRP = 4 * KT64;            // 36864: pass B group (Kh,Kl,Vh,Vl)
constexpr int SMEM_ATTN = 3 * BGRP;       // 110592 (covers OSA + 3*KT128 = 92160)

// ---------------------------------------------------------------------------
// Prepped fp16 hi/lo operands
// ---------------------------------------------------------------------------
__device__ __half g_xh[MROWS * HID], g_xl[MROWS * HID];
__device__ __half g_wh[4 * HID * HID], g_wl[4 * HID * HID];
__device__ __half g_qh[64 * SEQ * HDIM], g_ql[64 * SEQ * HDIM];
__device__ __half g_kh[64 * SEQ * HDIM], g_kl[64 * SEQ * HDIM];
__device__ __half g_vh[64 * SEQ * HDIM], g_vl[64 * SEQ * HDIM];
__device__ __half g_ch[MROWS * HID];     // ctx: hi only

// ---------------------------------------------------------------------------
__device__ __forceinline__ uint32_t smem_u32(const void* p) {
    uint32_t a;
    asm("{ .reg .u64 t; cvta.to.shared.u64 t, %1; cvt.u32.u64 %0, t; }"
        : "=r"(a) : "l"(p));
    return a;
}

__device__ __forceinline__ void ldsm4(uint32_t* r, uint32_t a) {
    asm volatile("ldmatrix.sync.aligned.m8n8.x4.shared.b16 {%0,%1,%2,%3}, [%4];"
                 : "=r"(r[0]), "=r"(r[1]), "=r"(r[2]), "=r"(r[3]) : "r"(a));
}
__device__ __forceinline__ void ldsm4t(uint32_t* r, uint32_t a) {
    asm volatile("ldmatrix.sync.aligned.m8n8.x4.trans.shared.b16 {%0,%1,%2,%3}, [%4];"
                 : "=r"(r[0]), "=r"(r[1]), "=r"(r[2]), "=r"(r[3]) : "r"(a));
}

#define MMA_F16(d, a, b0, b1)                                               \
    asm volatile(                                                           \
        "mma.sync.aligned.m16n8k16.row.col.f32.f16.f16.f32 "                \
        "{%0,%1,%2,%3}, {%4,%5,%6,%7}, {%8,%9}, {%0,%1,%2,%3};"             \
        : "+f"((d)[0]), "+f"((d)[1]), "+f"((d)[2]), "+f"((d)[3])            \
        : "r"((a)[0]), "r"((a)[1]), "r"((a)[2]), "r"((a)[3]),               \
          "r"(b0), "r"(b1))

__device__ __forceinline__ void cp16(uint32_t dst, const void* src) {
    asm volatile("cp.async.cg.shared.global [%0], [%1], 16;" :: "r"(dst), "l"(src));
}
#define CP_COMMIT asm volatile("cp.async.commit_group;" ::: "memory")
#define CP_WAIT1  asm volatile("cp.async.wait_group 1;" ::: "memory")
#define CP_WAIT0  asm volatile("cp.async.wait_group 0;" ::: "memory")

__device__ __forceinline__ uint32_t pack2(float x, float y) {
    __half2 h = __floats2half2_rn(x, y);
    return *(uint32_t*)&h;
}

__device__ __forceinline__ void pack_hl(float x, float y, uint32_t& h, uint32_t& l) {
    __half hx = __float2half_rn(x);
    __half hy = __float2half_rn(y);
    __half lx = __float2half_rn(x - __half2float(hx));
    __half ly = __float2half_rn(y - __half2float(hy));
    h = ((uint32_t)__half_as_ushort(hy) << 16) | __half_as_ushort(hx);
    l = ((uint32_t)__half_as_ushort(ly) << 16) | __half_as_ushort(lx);
}

// ---------------------------------------------------------------------------
// prep: split X and the 4 weight matrices into fp16 hi/lo once.
// ---------------------------------------------------------------------------
__global__ void __launch_bounds__(256) prep(
    const float* __restrict__ X,  const float* __restrict__ Wq,
    const float* __restrict__ Wk, const float* __restrict__ Wv,
    const float* __restrict__ Wo)
{
    const long long NX = (long long)MROWS * HID;
    long long i = (long long)blockIdx.x * 256 + threadIdx.x;
    float v; __half *dh, *dl; long long o;
    if (i < NX) {
        v = X[i]; dh = g_xh; dl = g_xl; o = i;
    } else {
        long long j = i - NX;
        int w = (int)(j >> 20);
        long long r = j & 1048575;
        if (w == 0) v = Wq[r]; else if (w == 1) v = Wk[r];
        else if (w == 2) v = Wv[r]; else v = Wo[r];
        dh = g_wh; dl = g_wl; o = j;
    }
    __half hb = __float2half_rn(v);
    dh[o] = hb;
    dl[o] = __float2half_rn(v - __half2float(hb));
}

// ---------------------------------------------------------------------------
// 3-term split-fp16 warp MMA over one 32-wide K chunk (qkv).
// ---------------------------------------------------------------------------
template <int MF, int NF>
__device__ __forceinline__ void mma_chunk3(float (&acc)[MF][NF][4],
                                           uint32_t aHi, uint32_t aLo,
                                           uint32_t bHi, uint32_t bLo,
                                           int mbase, int nbase, int lane)
{
    const int r16 = lane & 15;
    const int koL = (lane >> 4) * 16;
#pragma unroll
    for (int ks = 0; ks < 2; ks++) {
        const int kb = ks * 32 + koL;
        uint32_t FA[4 * MF], FB[2 * NF], FC[2 * NF];
#pragma unroll
        for (int mf = 0; mf < MF; mf++)
            ldsm4(&FA[4 * mf], aHi + (mbase + mf * 16 + r16) * (LDT * 2) + kb);
#pragma unroll
        for (int nb = 0; nb < NF / 2; nb++)
            ldsm4(&FB[4 * nb], bHi + (nbase + nb * 16 + r16) * (LDT * 2) + kb);
#pragma unroll
        for (int mf = 0; mf < MF; mf++)
#pragma unroll
            for (int nf = 0; nf < NF; nf++)
                MMA_F16(acc[mf][nf], &FA[4 * mf],
                        FB[4 * (nf >> 1) + (nf & 1)], FB[4 * (nf >> 1) + 2 + (nf & 1)]);
#pragma unroll
        for (int nb = 0; nb < NF / 2; nb++)
            ldsm4(&FC[4 * nb], bLo + (nbase + nb * 16 + r16) * (LDT * 2) + kb);
#pragma unroll
        for (int mf = 0; mf < MF; mf++)
#pragma unroll
            for (int nf = 0; nf < NF; nf++)
                MMA_F16(acc[mf][nf], &FA[4 * mf],
                        FC[4 * (nf >> 1) + (nf & 1)], FC[4 * (nf >> 1) + 2 + (nf & 1)]);
#pragma unroll
        for (int mf = 0; mf < MF; mf++)
            ldsm4(&FA[4 * mf], aLo + (mbase + mf * 16 + r16) * (LDT * 2) + kb);
#pragma unroll
        for (int mf = 0; mf < MF; mf++)
#pragma unroll
            for (int nf = 0; nf < NF; nf++)
                MMA_F16(acc[mf][nf], &FA[4 * mf],
                        FB[4 * (nf >> 1) + (nf & 1)], FB[4 * (nf >> 1) + 2 + (nf & 1)]);
    }
}

// 2-term variant: A hi only, B hi+lo (out projection).
template <int MF, int NF>
__device__ __forceinline__ void mma_chunk2(float (&acc)[MF][NF][4],
                                           uint32_t aHi,
                                           uint32_t bHi, uint32_t bLo,
                                           int mbase, int nbase, int lane)
{
    const int r16 = lane & 15;
    const int koL = (lane >> 4) * 16;
#pragma unroll
    for (int ks = 0; ks < 2; ks++) {
        const int kb = ks * 32 + koL;
        uint32_t FA[4 * MF], FB[2 * NF];
#pragma unroll
        for (int mf = 0; mf < MF; mf++)
            ldsm4(&FA[4 * mf], aHi + (mbase + mf * 16 + r16) * (LDT * 2) + kb);
#pragma unroll
        for (int nb = 0; nb < NF / 2; nb++)
            ldsm4(&FB[4 * nb], bHi + (nbase + nb * 16 + r16) * (LDT * 2) + kb);
#pragma unroll
        for (int mf = 0; mf < MF; mf++)
#pragma unroll
            for (int nf = 0; nf < NF; nf++)
                MMA_F16(acc[mf][nf], &FA[4 * mf],
                        FB[4 * (nf >> 1) + (nf & 1)], FB[4 * (nf >> 1) + 2 + (nf & 1)]);
#pragma unroll
        for (int nb = 0; nb < NF / 2; nb++)
            ldsm4(&FB[4 * nb], bLo + (nbase + nb * 16 + r16) * (LDT * 2) + kb);
#pragma unroll
        for (int mf = 0; mf < MF; mf++)
#pragma unroll
            for (int nf = 0; nf < NF; nf++)
                MMA_F16(acc[mf][nf], &FA[4 * mf],
                        FB[4 * (nf >> 1) + (nf & 1)], FB[4 * (nf >> 1) + 2 + (nf & 1)]);
    }
}

// cp.async a 128x32 fp16 tile (ld = HID) into LDT=40 smem (256 thr)
__device__ __forceinline__ void cp_tile32(const __half* __restrict__ src,
                                          uint32_t dst, int tid) {
#pragma unroll
    for (int i = 0; i < 2; i++) {
        int id = tid + i * 256;
        int r = id >> 2, c = id & 3;
        cp16(dst + r * (LDT * 2) + c * 16, src + (long long)r * HID + c * 8);
    }
}

// ---------------------------------------------------------------------------
// QKV projection (3-term, 2-stage, SINGLE sync: cp issued after the barrier
// targets the buffer all warps finished reading before it).
// grid(8, 64, 3), 256 thr.
// ---------------------------------------------------------------------------
__global__ void __launch_bounds__(256, 2) mm_qkv(
    const float* __restrict__ bq, const float* __restrict__ bk,
    const float* __restrict__ bv)
{
    extern __shared__ char sm[];
    const int z = blockIdx.z;
    const float* bias = (z == 0) ? bq : (z == 1) ? bk : bv;
    __half* dsth = (z == 0) ? g_qh : (z == 1) ? g_kh : g_vh;
    __half* dstl = (z == 0) ? g_ql : (z == 1) ? g_kl : g_vl;

    const int tid = threadIdx.x, lane = tid & 31, wid = tid >> 5;
    const int mw = wid >> 2, nw = wid & 3;
    const int m0 = blockIdx.y * 128, n0 = blockIdx.x * 128;
    const __half* Ah = g_xh + (long long)m0 * HID;
    const __half* Al = g_xl + (long long)m0 * HID;
    const __half* Bh = g_wh + (long long)z * HID * HID + (long long)n0 * HID;
    const __half* Bl = g_wl + (long long)z * HID * HID + (long long)n0 * HID;
    const uint32_t s0 = smem_u32(sm);

    float acc[4][4][4];
#pragma unroll
    for (int i = 0; i < 4; i++)
#pragma unroll
        for (int j = 0; j < 4; j++)
#pragma unroll
            for (int q = 0; q < 4; q++) acc[i][j][q] = 0.f;

    cp_tile32(Ah, s0 + 0 * TILE_B, tid);
    cp_tile32(Al, s0 + 1 * TILE_B, tid);
    cp_tile32(Bh, s0 + 2 * TILE_B, tid);
    cp_tile32(Bl, s0 + 3 * TILE_B, tid);
    CP_COMMIT;

    for (int c = 0; c < 32; c++) {
        CP_WAIT0;            // group c complete (issued last iteration)
        __syncthreads();     // all warps done reading the other buffer
        if (c + 1 < 32) {    // prefetch into the buffer just released
            uint32_t nb = s0 + ((c + 1) & 1) * GBUF;
            cp_tile32(Ah + (c + 1) * 32, nb + 0 * TILE_B, tid);
            cp_tile32(Al + (c + 1) * 32, nb + 1 * TILE_B, tid);
            cp_tile32(Bh + (c + 1) * 32, nb + 2 * TILE_B, tid);
            cp_tile32(Bl + (c + 1) * 32, nb + 3 * TILE_B, tid);
            CP_COMMIT;
        }
        uint32_t buf = s0 + (c & 1) * GBUF;
        mma_chunk3<4, 4>(acc, buf, buf + TILE_B, buf + 2 * TILE_B, buf + 3 * TILE_B,
                         mw * 64, nw * 32, lane);
    }

    const int g = lane >> 2, tig = lane & 3;
#pragma unroll
    for (int mf = 0; mf < 4; mf++) {
#pragma unroll
        for (int half = 0; half < 2; half++) {
            const int m = m0 + mw * 64 + mf * 16 + g + half * 8;
            const int b = m >> 11, s = m & 2047;
#pragma unroll
            for (int nf = 0; nf < 4; nf++) {
                const int n = n0 + nw * 32 + nf * 8 + tig * 2;
                const int h = n >> 6, d = n & 63;
                float vx = acc[mf][nf][half * 2 + 0] + bias[n + 0];
                float vy = acc[mf][nf][half * 2 + 1] + bias[n + 1];
                uint32_t hw, lw;
                pack_hl(vx, vy, hw, lw);
                long long idx = ((long long)(b * NHEAD + h) * SEQ + s) * HDIM + d;
                *(uint32_t*)(dsth + idx) = hw;
                *(uint32_t*)(dstl + idx) = lw;
            }
        }
    }
}

// ---------------------------------------------------------------------------
// Attention, 256 threads, 128-row Q, 2 CTAs/SM, single-sync rings.
// Pass A: 128-row K tiles (16 iters).  Pass B: 64-row KV groups (32 iters).
// grid(16, 64).
// ---------------------------------------------------------------------------
__device__ __forceinline__ void cp_kv64(const __half* __restrict__ src,
                                        uint32_t dst, int tid) {
#pragma unroll
    for (int i = 0; i < 2; i++) {
        int id = tid + i * 256;
        int r = id >> 3, c = id & 7;
        cp16(dst + r * LDA_B + c * 16, src + (long long)r * HDIM + c * 8);
    }
}
__device__ __forceinline__ void cp_t128(const __half* __restrict__ src,
                                        uint32_t dst, int tid) {
#pragma unroll
    for (int i = 0; i < 4; i++) {
        int id = tid + i * 256;
        int r = id >> 3, c = id & 7;
        cp16(dst + r * LDA_B + c * 16, src + (long long)r * HDIM + c * 8);
    }
}

// 3-term S tile: Qh*Kh + Qh*Kl + Ql*Kh   (pass B)
__device__ __forceinline__ void s_tile3(float* acc,
                                        const uint32_t* FQh, const uint32_t* FQl,
                                        uint32_t kh, uint32_t kl, int nfp, int lane)
{
    const int r16 = lane & 15;
    const int koL = (lane >> 4) * 16;
    const uint32_t rowoff = (uint32_t)(nfp * 16 + r16) * LDA_B;
#pragma unroll
    for (int ks = 0; ks < 4; ks++) {
        uint32_t FBh[4], FBl[4];
        ldsm4(FBh, kh + rowoff + ks * 32 + koL);
        ldsm4(FBl, kl + rowoff + ks * 32 + koL);
        MMA_F16(acc,     &FQh[4 * ks], FBh[0], FBh[2]);
        MMA_F16(acc + 4, &FQh[4 * ks], FBh[1], FBh[3]);
        MMA_F16(acc,     &FQh[4 * ks], FBl[0], FBl[2]);
        MMA_F16(acc + 4, &FQh[4 * ks], FBl[1], FBl[3]);
        MMA_F16(acc,     &FQl[4 * ks], FBh[0], FBh[2]);
        MMA_F16(acc + 4, &FQl[4 * ks], FBh[1], FBh[3]);
    }
}

// 2-term S tile for pass A sums: Qh*Kh + Ql*Kh
__device__ __forceinline__ void s_tile2(float* acc,
                                        const uint32_t* FQh, const uint32_t* FQl,
                                        uint32_t kh, int nfp, int lane)
{
    const int r16 = lane & 15;
    const int koL = (lane >> 4) * 16;
    const uint32_t rowoff = (uint32_t)(nfp * 16 + r16) * LDA_B;
#pragma unroll
    for (int ks = 0; ks < 4; ks++) {
        uint32_t FBh[4];
        ldsm4(FBh, kh + rowoff + ks * 32 + koL);
        MMA_F16(acc,     &FQh[4 * ks], FBh[0], FBh[2]);
        MMA_F16(acc + 4, &FQh[4 * ks], FBh[1], FBh[3]);
        MMA_F16(acc,     &FQl[4 * ks], FBh[0], FBh[2]);
        MMA_F16(acc + 4, &FQl[4 * ks], FBh[1], FBh[3]);
    }
}

__global__ void __launch_bounds__(256, 2) attn(float* __restrict__ probs)
{
    extern __shared__ char sm[];
    const int tid = threadIdx.x, lane = tid & 31, w = tid >> 5;   // w: 0..7
    const int g = lane >> 2, tig = lane & 3;
    const int bh = blockIdx.y;
    const int m0 = blockIdx.x * 128;
    const uint32_t s0 = smem_u32(sm);

    const __half* Qh = g_qh + ((long long)bh * SEQ + m0) * HDIM;
    const __half* Ql = g_ql + ((long long)bh * SEQ + m0) * HDIM;
    const __half* Kh = g_kh + (long long)bh * SEQ * HDIM;
    const __half* Kl = g_kl + (long long)bh * SEQ * HDIM;
    const __half* Vh = g_vh + (long long)bh * SEQ * HDIM;
    const __half* Vl = g_vl + (long long)bh * SEQ * HDIM;
    float* C = probs + (long long)bh * SEQ * SEQ;

    // prologue: Q (group), K0 (128 rows) into pass-A slot 0 (group)
    cp_t128(Qh, s0 + OQH, tid);
    cp_t128(Ql, s0 + OQL, tid);
    CP_COMMIT;
    cp_t128(Kh, s0 + OSA, tid);
    CP_COMMIT;
    CP_WAIT1;           // Q done (K0 may be in flight)
    __syncthreads();

    uint32_t FQh[16], FQl[16];
    {
        const uint32_t arow = (uint32_t)(w * 16 + (lane & 15)) * LDA_B;
        const uint32_t koL = (lane >> 4) * 16;
#pragma unroll
        for (int ks = 0; ks < 4; ks++) {
            ldsm4(&FQh[4 * ks], s0 + OQH + arow + ks * 32 + koL);
            ldsm4(&FQl[4 * ks], s0 + OQL + arow + ks * 32 + koL);
        }
    }
    // Q smem region is dead from here on (fragments live in registers)

    // ------------- pass A: 3-slot 128-row Kh ring, single sync/iter -------
    float sum0 = 0.f, sum1 = 0.f;
    for (int j = 0; j < 16; j++) {
        if (j + 1 < 16)
            cp_t128(Kh + (long long)(j + 1) * 128 * HDIM,
                    s0 + OSA + ((j + 1) % 3) * KT128, tid);
        CP_COMMIT;
        CP_WAIT1;
        __syncthreads();
        const uint32_t kh = s0 + OSA + (j % 3) * KT128;
#pragma unroll
        for (int nfp = 0; nfp < 8; nfp++) {
            float acc[8] = {0.f, 0.f, 0.f, 0.f, 0.f, 0.f, 0.f, 0.f};
            s_tile2(acc, FQh, FQl, kh, nfp, lane);
            sum0 += __expf(acc[0]) + __expf(acc[1]) + __expf(acc[4]) + __expf(acc[5]);
            sum1 += __expf(acc[2]) + __expf(acc[3]) + __expf(acc[6]) + __expf(acc[7]);
        }
    }
#pragma unroll
    for (int o = 1; o <= 2; o <<= 1) {
        sum0 += __shfl_xor_sync(0xffffffffu, sum0, o);
        sum1 += __shfl_xor_sync(0xffffffffu, sum1, o);
    }
    const float ri0 = 1.0f / sum0;
    const float ri1 = 1.0f / sum1;

    // ---------------- pass B: 3-group KV ring (reuses Q region) -----------
    float ctx[8][4];
#pragma unroll
    for (int i = 0; i < 8; i++)
#pragma unroll
        for (int q = 0; q < 4; q++) ctx[i][q] = 0.f;

    // group 0 lives at offset 0 (= dead Q region): safe to fill while
    // stragglers finish pass A (they only touch OSA and registers).
    {
        uint32_t sl = s0;
        cp_kv64(Kh, sl, tid);
        cp_kv64(Kl, sl + KT64, tid);
        cp_kv64(Vh, sl + 2 * KT64, tid);
        cp_kv64(Vl, sl + 3 * KT64, tid);
        CP_COMMIT;
    }
    __syncthreads();   // all warps past pass A before group 1 overwrites OSA

    const long long rowg = m0 + w * 16 + g;
    const uint32_t vlanerow = (uint32_t)((lane & 7) + ((lane >> 4) & 1) * 8) * LDA_B
                              + ((lane >> 3) & 1) * 16;

    for (int j = 0; j < 32; j++) {
        if (j + 1 < 32) {
            uint32_t sl = s0 + ((j + 1) % 3) * BGRP;
            cp_kv64(Kh + (long long)(j + 1) * 64 * HDIM, sl, tid);
            cp_kv64(Kl + (long long)(j + 1) * 64 * HDIM, sl + KT64, tid);
            cp_kv64(Vh + (long long)(j + 1) * 64 * HDIM, sl + 2 * KT64, tid);
            cp_kv64(Vl + (long long)(j + 1) * 64 * HDIM, sl + 3 * KT64, tid);
        }
        CP_COMMIT;
        CP_WAIT1;
        __syncthreads();
        const uint32_t kh = s0 + (j % 3) * BGRP;
        const uint32_t kl = kh + KT64;
        const uint32_t vh = kh + 2 * KT64;
        const uint32_t vl = kh + 3 * KT64;

#pragma unroll
        for (int nfp = 0; nfp < 4; nfp++) {
            float acc[8] = {0.f, 0.f, 0.f, 0.f, 0.f, 0.f, 0.f, 0.f};
            s_tile3(acc, FQh, FQl, kh, kl, nfp, lane);
            float pE0 = __expf(acc[0]) * ri0, pE1 = __expf(acc[1]) * ri0;
            float pE2 = __expf(acc[2]) * ri1, pE3 = __expf(acc[3]) * ri1;
            float pO0 = __expf(acc[4]) * ri0, pO1 = __expf(acc[5]) * ri0;
            float pO2 = __expf(acc[6]) * ri1, pO3 = __expf(acc[7]) * ri1;
            float* Cr = C + rowg * SEQ + j * 64 + nfp * 16 + tig * 2;
            __stcs((float2*)Cr,                 make_float2(pE0, pE1));
            __stcs((float2*)(Cr + 8),           make_float2(pO0, pO1));
            __stcs((float2*)(Cr + 8 * SEQ),     make_float2(pE2, pE3));
            __stcs((float2*)(Cr + 8 * SEQ + 8), make_float2(pO2, pO3));
            uint32_t PAh[4];
            PAh[0] = pack2(pE0, pE1);
            PAh[1] = pack2(pE2, pE3);
            PAh[2] = pack2(pO0, pO1);
            PAh[3] = pack2(pO2, pO3);
            const uint32_t vbase = (uint32_t)(nfp * 16) * LDA_B + vlanerow;
#pragma unroll
            for (int gd = 0; gd < 4; gd++) {
                uint32_t FVh[4], FVl[4];
                ldsm4t(FVh, vh + vbase + gd * 32);
                ldsm4t(FVl, vl + vbase + gd * 32);
                MMA_F16(ctx[2 * gd + 0], PAh, FVh[0], FVh[2]);
                MMA_F16(ctx[2 * gd + 0], PAh, FVl[0], FVl[2]);
                MMA_F16(ctx[2 * gd + 1], PAh, FVh[1], FVh[3]);
                MMA_F16(ctx[2 * gd + 1], PAh, FVl[1], FVl[3]);
            }
        }
    }

    // ctx epilogue -> fp16 (hi only) [b][s][h*64+d]
    const int b = bh >> 4, h = bh & 15;
    const int s = m0 + w * 16 + g;
    const long long base = ((long long)(b * SEQ + s)) * HID + h * HDIM;
#pragma unroll
    for (int dnf = 0; dnf < 8; dnf++) {
        const int d = dnf * 8 + tig * 2;
        *(uint32_t*)(g_ch + base + d) = pack2(ctx[dnf][0], ctx[dnf][1]);
        *(uint32_t*)(g_ch + base + 8LL * HID + d) = pack2(ctx[dnf][2], ctx[dnf][3]);
    }
}

// ---------------------------------------------------------------------------
// Output projection + residual (2-term, 3-stage single-sync).  grid(8, 64).
// ---------------------------------------------------------------------------
__global__ void __launch_bounds__(256, 2) mm_out(
    const float* __restrict__ bo, const float* __restrict__ hidden,
    float* __restrict__ out)
{
    extern __shared__ char sm[];
    const int tid = threadIdx.x, lane = tid & 31, wid = tid >> 5;
    const int mw = wid >> 2, nw = wid & 3;
    const int m0 = blockIdx.y * 128, n0 = blockIdx.x * 128;
    const __half* Ah = g_ch + (long long)m0 * HID;
    const __half* Bh = g_wh + 3LL * HID * HID + (long long)n0 * HID;
    const __half* Bl = g_wl + 3LL * HID * HID + (long long)n0 * HID;
    const uint32_t s0 = smem_u32(sm);

    float acc[4][4][4];
#pragma unroll
    for (int i = 0; i < 4; i++)
#pragma unroll
        for (int j = 0; j < 4; j++)
#pragma unroll
            for (int q = 0; q < 4; q++) acc[i][j][q] = 0.f;

    cp_tile32(Ah, s0 + 0 * TILE_B, tid);
    cp_tile32(Bh, s0 + 1 * TILE_B, tid);
    cp_tile32(Bl, s0 + 2 * TILE_B, tid);
    CP_COMMIT;

    for (int c = 0; c < 32; c++) {
        if (c + 1 < 32) {
            uint32_t nb = s0 + ((c + 1) % 3) * GBUF2;
            cp_tile32(Ah + (c + 1) * 32, nb + 0 * TILE_B, tid);
            cp_tile32(Bh + (c + 1) * 32, nb + 1 * TILE_B, tid);
            cp_tile32(Bl + (c + 1) * 32, nb + 2 * TILE_B, tid);
        }
        CP_COMMIT;
        CP_WAIT1;
        __syncthreads();
        uint32_t buf = s0 + (c % 3) * GBUF2;
        mma_chunk2<4, 4>(acc, buf, buf + TILE_B, buf + 2 * TILE_B,
                         mw * 64, nw * 32, lane);
        // single-sync: 3-stage ring, distance-1 prefetch is race-free
    }

    const int g = lane >> 2, tig = lane & 3;
#pragma unroll
    for (int mf = 0; mf < 4; mf++) {
#pragma unroll
        for (int half = 0; half < 2; half++) {
            const long long m = m0 + mw * 64 + mf * 16 + g + half * 8;
#pragma unroll
            for (int nf = 0; nf < 4; nf++) {
                const int n = n0 + nw * 32 + nf * 8 + tig * 2;
                float2 hd = *(const float2*)(hidden + m * HID + n);
                float2 st;
                st.x = acc[mf][nf][half * 2 + 0] + bo[n + 0] + hd.x;
                st.y = acc[mf][nf][half * 2 + 1] + bo[n + 1] + hd.y;
                *(float2*)(out + m * HID + n) = st;
            }
        }
    }
}

// ---------------------------------------------------------------------------
extern "C" void kernel_launch(void* const* d_in, const int* in_sizes, int n_in,
                              void* d_out, int out_size)
{
    const float* X  = (const float*)d_in[0];
    const float* Wq = (const float*)d_in[1];
    const float* bq = (const float*)d_in[2];
    const float* Wk = (const float*)d_in[3];
    const float* bk = (const float*)d_in[4];
    const float* Wv = (const float*)d_in[5];
    const float* bv = (const float*)d_in[6];
    const float* Wo = (const float*)d_in[7];
    const float* bo = (const float*)d_in[8];

    float* out   = (float*)d_out;
    float* probs = out + OUT_ELEMS;

    cudaFuncSetAttribute(mm_qkv, cudaFuncAttributeMaxDynamicSharedMemorySize, SMEM_G);
    cudaFuncSetAttribute(mm_out, cudaFuncAttributeMaxDynamicSharedMemorySize, SMEM_G2);
    cudaFuncSetAttribute(attn,   cudaFuncAttributeMaxDynamicSharedMemorySize, SMEM_ATTN);

    const long long NPREP = (long long)MROWS * HID + 4LL * HID * HID;
    prep<<<(unsigned)((NPREP + 255) / 256), 256>>>(X, Wq, Wk, Wv, Wo);
    mm_qkv<<<dim3(HID / 128, MROWS / 128, 3), 256, SMEM_G>>>(bq, bk, bv);
    attn<<<dim3(SEQ / 128, BATCH * NHEAD), 256, SMEM_ATTN>>>(probs);
    mm_out<<<dim3(HID / 128, MROWS / 128), 256, SMEM_G2>>>(bo, X, out);
}